// round 1
// baseline (speedup 1.0000x reference)
#include <cuda_runtime.h>
#include <math.h>

#define BATCH 128
#define SEQ   512
#define NDIM  1024   // INPUT == HIDDEN == OUTPUT == 1024

// Scratch (allocation-free: static __device__ globals)
__device__ float g_xp[(size_t)BATCH * SEQ * NDIM];  // 256 MB: x @ W_xh + b_h
__device__ float g_h[2][BATCH * NDIM];              // ping-pong hidden state

// ---------------------------------------------------------------------------
// Zero-init h0
// ---------------------------------------------------------------------------
__global__ void zero_h0() {
    int idx = blockIdx.x * blockDim.x + threadIdx.x;
    if (idx < BATCH * NDIM) g_h[0][idx] = 0.0f;
}

// ---------------------------------------------------------------------------
// XP GEMM: g_xp[M,N] = A[M,K] * B[K,N] + bias[N]
// M = 65536, N = K = 1024. BM=BN=128, BK=8, TM=TN=8, 256 threads.
// ---------------------------------------------------------------------------
__global__ void __launch_bounds__(256) xp_gemm(const float* __restrict__ A,
                                               const float* __restrict__ B,
                                               const float* __restrict__ bias) {
    const int K = NDIM, N = NDIM;
    __shared__ float As[8 * 132];   // transposed, padded stride 132 (16B-aligned, conflict-free)
    __shared__ float Bs[8 * 128];

    const int tid  = threadIdx.x;
    const int cCol = blockIdx.x;    // N / 128 = 8
    const int cRow = blockIdx.y;    // M / 128 = 512

    const int threadCol = tid % 16; // 16 x 16 thread grid, 8x8 micro-tile each
    const int threadRow = tid / 16;

    const float* Ab = A + (size_t)cRow * 128 * K;
    const float* Bb = B + cCol * 128;

    const int rA = tid / 2;          // 0..127
    const int cA = (tid % 2) * 4;    // 0 or 4
    const int rB = tid / 32;         // 0..7
    const int cB = (tid % 32) * 4;   // 0..124

    float acc[8][8];
#pragma unroll
    for (int i = 0; i < 8; i++)
#pragma unroll
        for (int j = 0; j < 8; j++) acc[i][j] = 0.0f;

    float regM[8], regN[8];

    for (int bk = 0; bk < K; bk += 8) {
        float4 a = *(const float4*)(Ab + (size_t)rA * K + bk + cA);
        As[(cA + 0) * 132 + rA] = a.x;
        As[(cA + 1) * 132 + rA] = a.y;
        As[(cA + 2) * 132 + rA] = a.z;
        As[(cA + 3) * 132 + rA] = a.w;
        *(float4*)(Bs + rB * 128 + cB) =
            *(const float4*)(Bb + (size_t)(bk + rB) * N + cB);
        __syncthreads();

#pragma unroll
        for (int d = 0; d < 8; d++) {
            *(float4*)(regM)     = *(const float4*)(As + d * 132 + threadRow * 8);
            *(float4*)(regM + 4) = *(const float4*)(As + d * 132 + threadRow * 8 + 4);
            *(float4*)(regN)     = *(const float4*)(Bs + d * 128 + threadCol * 8);
            *(float4*)(regN + 4) = *(const float4*)(Bs + d * 128 + threadCol * 8 + 4);
#pragma unroll
            for (int i = 0; i < 8; i++)
#pragma unroll
                for (int j = 0; j < 8; j++)
                    acc[i][j] += regM[i] * regN[j];
        }
        __syncthreads();
    }

    const int colBase = cCol * 128 + threadCol * 8;
    float4 bv0 = *(const float4*)(bias + colBase);
    float4 bv1 = *(const float4*)(bias + colBase + 4);
#pragma unroll
    for (int i = 0; i < 8; i++) {
        size_t row = (size_t)cRow * 128 + threadRow * 8 + i;
        float* Crow = g_xp + row * NDIM + colBase;
        float4 v0, v1;
        v0.x = acc[i][0] + bv0.x; v0.y = acc[i][1] + bv0.y;
        v0.z = acc[i][2] + bv0.z; v0.w = acc[i][3] + bv0.w;
        v1.x = acc[i][4] + bv1.x; v1.y = acc[i][5] + bv1.y;
        v1.z = acc[i][6] + bv1.z; v1.w = acc[i][7] + bv1.w;
        *(float4*)(Crow)     = v0;
        *(float4*)(Crow + 4) = v1;
    }
}

// ---------------------------------------------------------------------------
// RNN step: g_h[t+1 & 1] = tanh(xp[:, t, :] + g_h[t & 1] @ W_hh)
// C: 128 x 1024. Tile 32x32, K full 1024 in BK=32 chunks.
// grid (32, 4) = 128 CTAs, 128 threads, 2x4 register tile per thread.
// ---------------------------------------------------------------------------
__global__ void __launch_bounds__(128) rnn_step(const float* __restrict__ W, int t) {
    __shared__ float As[32 * 34];   // transposed h tile, stride 34 (8B-aligned float2)
    __shared__ float Bs[32 * 32];

    const float* __restrict__ H = g_h[t & 1];
    float* __restrict__ Hout    = g_h[(t + 1) & 1];

    const int tid = threadIdx.x;
    const int bx  = blockIdx.x;   // col tile 0..31
    const int by  = blockIdx.y;   // row tile 0..3

    const int rI = tid / 8;        // 0..15 (load rows rI, rI+16)
    const int cI = (tid % 8) * 4;  // 0..28

    const int tr = tid / 8;        // compute rows: tr*2, tr*2+1
    const int tc = tid % 8;        // compute cols: tc*4 .. tc*4+3

    float acc[2][4];
#pragma unroll
    for (int i = 0; i < 2; i++)
#pragma unroll
        for (int j = 0; j < 4; j++) acc[i][j] = 0.0f;

    for (int bk = 0; bk < NDIM; bk += 32) {
#pragma unroll
        for (int rr = 0; rr < 2; rr++) {
            int r = rI + rr * 16;
            float4 a = *(const float4*)(H + (by * 32 + r) * NDIM + bk + cI);
            As[(cI + 0) * 34 + r] = a.x;
            As[(cI + 1) * 34 + r] = a.y;
            As[(cI + 2) * 34 + r] = a.z;
            As[(cI + 3) * 34 + r] = a.w;
            *(float4*)(Bs + r * 32 + cI) =
                *(const float4*)(W + (size_t)(bk + r) * NDIM + bx * 32 + cI);
        }
        __syncthreads();

#pragma unroll
        for (int k = 0; k < 32; k++) {
            float2 av = *(const float2*)(As + k * 34 + tr * 2);
            float4 bv = *(const float4*)(Bs + k * 32 + tc * 4);
            acc[0][0] += av.x * bv.x; acc[0][1] += av.x * bv.y;
            acc[0][2] += av.x * bv.z; acc[0][3] += av.x * bv.w;
            acc[1][0] += av.y * bv.x; acc[1][1] += av.y * bv.y;
            acc[1][2] += av.y * bv.z; acc[1][3] += av.y * bv.w;
        }
        __syncthreads();
    }

    const int col = bx * 32 + tc * 4;
#pragma unroll
    for (int i = 0; i < 2; i++) {
        int row = by * 32 + tr * 2 + i;   // batch index
        const float* xp = g_xp + ((size_t)row * SEQ + t) * NDIM + col;
        float4 x4 = *(const float4*)xp;
        float4 v;
        v.x = tanhf(acc[i][0] + x4.x);
        v.y = tanhf(acc[i][1] + x4.y);
        v.z = tanhf(acc[i][2] + x4.z);
        v.w = tanhf(acc[i][3] + x4.w);
        *(float4*)(Hout + row * NDIM + col) = v;
    }
}

// ---------------------------------------------------------------------------
// Final: out = h_final @ W_hy + b_y   (h_final lives in g_h[0] after 512 steps)
// ---------------------------------------------------------------------------
__global__ void __launch_bounds__(128) rnn_final(const float* __restrict__ W,
                                                 const float* __restrict__ bias,
                                                 float* __restrict__ out) {
    __shared__ float As[32 * 34];
    __shared__ float Bs[32 * 32];

    const float* __restrict__ H = g_h[0];  // 512 steps -> parity back to 0

    const int tid = threadIdx.x;
    const int bx  = blockIdx.x;
    const int by  = blockIdx.y;

    const int rI = tid / 8;
    const int cI = (tid % 8) * 4;
    const int tr = tid / 8;
    const int tc = tid % 8;

    float acc[2][4];
#pragma unroll
    for (int i = 0; i < 2; i++)
#pragma unroll
        for (int j = 0; j < 4; j++) acc[i][j] = 0.0f;

    for (int bk = 0; bk < NDIM; bk += 32) {
#pragma unroll
        for (int rr = 0; rr < 2; rr++) {
            int r = rI + rr * 16;
            float4 a = *(const float4*)(H + (by * 32 + r) * NDIM + bk + cI);
            As[(cI + 0) * 34 + r] = a.x;
            As[(cI + 1) * 34 + r] = a.y;
            As[(cI + 2) * 34 + r] = a.z;
            As[(cI + 3) * 34 + r] = a.w;
            *(float4*)(Bs + r * 32 + cI) =
                *(const float4*)(W + (size_t)(bk + r) * NDIM + bx * 32 + cI);
        }
        __syncthreads();

#pragma unroll
        for (int k = 0; k < 32; k++) {
            float2 av = *(const float2*)(As + k * 34 + tr * 2);
            float4 bv = *(const float4*)(Bs + k * 32 + tc * 4);
            acc[0][0] += av.x * bv.x; acc[0][1] += av.x * bv.y;
            acc[0][2] += av.x * bv.z; acc[0][3] += av.x * bv.w;
            acc[1][0] += av.y * bv.x; acc[1][1] += av.y * bv.y;
            acc[1][2] += av.y * bv.z; acc[1][3] += av.y * bv.w;
        }
        __syncthreads();
    }

    const int col = bx * 32 + tc * 4;
    float4 bv4 = *(const float4*)(bias + col);
#pragma unroll
    for (int i = 0; i < 2; i++) {
        int row = by * 32 + tr * 2 + i;
        float4 v;
        v.x = acc[i][0] + bv4.x;
        v.y = acc[i][1] + bv4.y;
        v.z = acc[i][2] + bv4.z;
        v.w = acc[i][3] + bv4.w;
        *(float4*)(out + row * NDIM + col) = v;
    }
}

// ---------------------------------------------------------------------------
// kernel_launch — graph-capturable: kernel launches only
// ---------------------------------------------------------------------------
extern "C" void kernel_launch(void* const* d_in, const int* in_sizes, int n_in,
                              void* d_out, int out_size) {
    (void)in_sizes; (void)n_in; (void)out_size;
    const float* x    = (const float*)d_in[0];
    const float* W_xh = (const float*)d_in[1];
    const float* W_hh = (const float*)d_in[2];
    const float* b_h  = (const float*)d_in[3];
    const float* W_hy = (const float*)d_in[4];
    const float* b_y  = (const float*)d_in[5];
    float* out = (float*)d_out;

    zero_h0<<<(BATCH * NDIM + 511) / 512, 512>>>();

    dim3 gridXP(NDIM / 128, (BATCH * SEQ) / 128);   // (8, 512)
    xp_gemm<<<gridXP, 256>>>(x, W_xh, b_h);

    dim3 gridStep(NDIM / 32, BATCH / 32);           // (32, 4)
    for (int t = 0; t < SEQ; t++) {
        rnn_step<<<gridStep, 128>>>(W_hh, t);
    }

    rnn_final<<<gridStep, 128>>>(W_hy, b_y, out);
}

// round 2
// speedup vs baseline: 1.5569x; 1.5569x over previous
#include <cuda_runtime.h>
#include <math.h>

#define BATCH 128
#define SEQ   512
#define NDIM  1024   // INPUT == HIDDEN == OUTPUT == 1024
#define SPLITK 4
#define KCHUNK (NDIM / SPLITK)   // 256

// Scratch (allocation-free: static __device__ globals)
__device__ float g_xp[(size_t)BATCH * SEQ * NDIM];   // 256 MB: x @ W_xh + b_h
__device__ float g_h[2][BATCH * NDIM];               // ping-pong hidden state
__device__ float g_part[SPLITK][BATCH * NDIM];       // split-K partials (2 MB)
__device__ int   g_cnt[32];                          // per-tile arrival counters (zero-init)

// ---------------------------------------------------------------------------
// Zero-init h0
// ---------------------------------------------------------------------------
__global__ void zero_h0() {
    int idx = blockIdx.x * blockDim.x + threadIdx.x;
    if (idx < BATCH * NDIM) g_h[0][idx] = 0.0f;
}

// ---------------------------------------------------------------------------
// XP GEMM: g_xp[M,N] = A[M,K] * B[K,N] + bias[N]
// M = 65536, N = K = 1024. BM=BN=128, BK=8, TM=TN=8, 256 threads.
// (near fp32-FMA floor; tensor-core rewrite is a later round)
// ---------------------------------------------------------------------------
__global__ void __launch_bounds__(256) xp_gemm(const float* __restrict__ A,
                                               const float* __restrict__ B,
                                               const float* __restrict__ bias) {
    const int K = NDIM, N = NDIM;
    __shared__ float As[8 * 132];
    __shared__ float Bs[8 * 128];

    const int tid  = threadIdx.x;
    const int cCol = blockIdx.x;
    const int cRow = blockIdx.y;

    const int threadCol = tid % 16;
    const int threadRow = tid / 16;

    const float* Ab = A + (size_t)cRow * 128 * K;
    const float* Bb = B + cCol * 128;

    const int rA = tid / 2;
    const int cA = (tid % 2) * 4;
    const int rB = tid / 32;
    const int cB = (tid % 32) * 4;

    float acc[8][8];
#pragma unroll
    for (int i = 0; i < 8; i++)
#pragma unroll
        for (int j = 0; j < 8; j++) acc[i][j] = 0.0f;

    float regM[8], regN[8];

    for (int bk = 0; bk < K; bk += 8) {
        float4 a = *(const float4*)(Ab + (size_t)rA * K + bk + cA);
        As[(cA + 0) * 132 + rA] = a.x;
        As[(cA + 1) * 132 + rA] = a.y;
        As[(cA + 2) * 132 + rA] = a.z;
        As[(cA + 3) * 132 + rA] = a.w;
        *(float4*)(Bs + rB * 128 + cB) =
            *(const float4*)(Bb + (size_t)(bk + rB) * N + cB);
        __syncthreads();

#pragma unroll
        for (int d = 0; d < 8; d++) {
            *(float4*)(regM)     = *(const float4*)(As + d * 132 + threadRow * 8);
            *(float4*)(regM + 4) = *(const float4*)(As + d * 132 + threadRow * 8 + 4);
            *(float4*)(regN)     = *(const float4*)(Bs + d * 128 + threadCol * 8);
            *(float4*)(regN + 4) = *(const float4*)(Bs + d * 128 + threadCol * 8 + 4);
#pragma unroll
            for (int i = 0; i < 8; i++)
#pragma unroll
                for (int j = 0; j < 8; j++)
                    acc[i][j] += regM[i] * regN[j];
        }
        __syncthreads();
    }

    const int colBase = cCol * 128 + threadCol * 8;
    float4 bv0 = *(const float4*)(bias + colBase);
    float4 bv1 = *(const float4*)(bias + colBase + 4);
#pragma unroll
    for (int i = 0; i < 8; i++) {
        size_t row = (size_t)cRow * 128 + threadRow * 8 + i;
        float* Crow = g_xp + row * NDIM + colBase;
        float4 v0, v1;
        v0.x = acc[i][0] + bv0.x; v0.y = acc[i][1] + bv0.y;
        v0.z = acc[i][2] + bv0.z; v0.w = acc[i][3] + bv0.w;
        v1.x = acc[i][4] + bv1.x; v1.y = acc[i][5] + bv1.y;
        v1.z = acc[i][6] + bv1.z; v1.w = acc[i][7] + bv1.w;
        *(float4*)(Crow)     = v0;
        *(float4*)(Crow + 4) = v1;
    }
}

// ---------------------------------------------------------------------------
// RNN step, fused split-K + last-CTA reduce + tanh.
// C[128,1024] = H @ W. Tile 64x64, 256 threads (16x16, 4x4 micro-tile),
// grid (16 ntile, 2 mtile, 4 ksplit) = 128 CTAs (one per SM).
// Each CTA writes a 64x64 partial; the last CTA per tile (atomic counter)
// sums the SPLITK partials in fixed order, adds xp[:,t,:], tanh, writes h.
// ---------------------------------------------------------------------------
__global__ void __launch_bounds__(256) rnn_step(const float* __restrict__ W, int t) {
    __shared__ float As[2][16 * 68];   // As[buf][kk*68 + m]  (transposed, padded)
    __shared__ float Bs[2][16 * 64];   // Bs[buf][kk*64 + n]
    __shared__ int s_last;

    const float* __restrict__ H = g_h[t & 1];
    float* __restrict__ Hout    = g_h[(t + 1) & 1];

    const int tid = threadIdx.x;
    const int bn  = blockIdx.x;     // 0..15
    const int bm  = blockIdx.y;     // 0..1
    const int bz  = blockIdx.z;     // 0..3
    const int kbase = bz * KCHUNK;

    const int tx = tid % 16;        // N micro (4 cols)
    const int ty = tid / 16;        // M micro (4 rows)

    // loader indices
    const int rA = tid >> 2;              // 0..63 (row of A tile)
    const int cA = (tid & 3) * 4;         // 0,4,8,12 (k offset)
    const int rB = tid >> 4;              // 0..15 (k row of B tile)
    const int cB = (tid & 15) * 4;        // 0..60

    const float* Aptr = H + (size_t)(bm * 64 + rA) * NDIM + kbase + cA;
    const float* Bptr = W + (size_t)(kbase + rB) * NDIM + bn * 64 + cB;

    float acc[4][4];
#pragma unroll
    for (int i = 0; i < 4; i++)
#pragma unroll
        for (int j = 0; j < 4; j++) acc[i][j] = 0.0f;

    // prologue: load tile 0
    float4 pA = *(const float4*)(Aptr);
    float4 pB = *(const float4*)(Bptr);
    As[0][(cA + 0) * 68 + rA] = pA.x;
    As[0][(cA + 1) * 68 + rA] = pA.y;
    As[0][(cA + 2) * 68 + rA] = pA.z;
    As[0][(cA + 3) * 68 + rA] = pA.w;
    *(float4*)(&Bs[0][rB * 64 + cB]) = pB;
    __syncthreads();

    const int NKO = KCHUNK / 16;   // 16 outer iterations
#pragma unroll 1
    for (int ko = 0; ko < NKO; ko++) {
        const int buf = ko & 1;
        if (ko < NKO - 1) {
            pA = *(const float4*)(Aptr + (ko + 1) * 16);
            pB = *(const float4*)(Bptr + (size_t)(ko + 1) * 16 * NDIM);
        }
#pragma unroll
        for (int kk = 0; kk < 16; kk++) {
            float4 rM = *(const float4*)(&As[buf][kk * 68 + ty * 4]);
            float4 rN = *(const float4*)(&Bs[buf][kk * 64 + tx * 4]);
            acc[0][0] += rM.x * rN.x; acc[0][1] += rM.x * rN.y;
            acc[0][2] += rM.x * rN.z; acc[0][3] += rM.x * rN.w;
            acc[1][0] += rM.y * rN.x; acc[1][1] += rM.y * rN.y;
            acc[1][2] += rM.y * rN.z; acc[1][3] += rM.y * rN.w;
            acc[2][0] += rM.z * rN.x; acc[2][1] += rM.z * rN.y;
            acc[2][2] += rM.z * rN.z; acc[2][3] += rM.z * rN.w;
            acc[3][0] += rM.w * rN.x; acc[3][1] += rM.w * rN.y;
            acc[3][2] += rM.w * rN.z; acc[3][3] += rM.w * rN.w;
        }
        if (ko < NKO - 1) {
            const int nbuf = buf ^ 1;
            As[nbuf][(cA + 0) * 68 + rA] = pA.x;
            As[nbuf][(cA + 1) * 68 + rA] = pA.y;
            As[nbuf][(cA + 2) * 68 + rA] = pA.z;
            As[nbuf][(cA + 3) * 68 + rA] = pA.w;
            *(float4*)(&Bs[nbuf][rB * 64 + cB]) = pB;
            __syncthreads();
        }
    }

    // write partial tile
    float* part = g_part[bz];
#pragma unroll
    for (int i = 0; i < 4; i++) {
        int row = bm * 64 + ty * 4 + i;
        int col = bn * 64 + tx * 4;
        float4 v;
        v.x = acc[i][0]; v.y = acc[i][1]; v.z = acc[i][2]; v.w = acc[i][3];
        *(float4*)(part + (size_t)row * NDIM + col) = v;
    }

    __threadfence();
    __syncthreads();
    const int tile = bm * 16 + bn;
    if (tid == 0) s_last = atomicAdd(&g_cnt[tile], 1);
    __syncthreads();

    if (s_last == SPLITK - 1) {
        __threadfence();   // acquire: make all partials visible
        // reduce 64x64 tile: 1024 float4s / 256 threads = 4 each
#pragma unroll
        for (int p = 0; p < 4; p++) {
            int q   = tid + p * 256;       // 0..1023
            int r   = q >> 4;              // 0..63
            int c4  = (q & 15) * 4;        // 0..60
            int row = bm * 64 + r;         // batch index
            int col = bn * 64 + c4;        // hidden index
            size_t off = (size_t)row * NDIM + col;
            float4 s0 = *(const float4*)(g_part[0] + off);
            float4 s1 = *(const float4*)(g_part[1] + off);
            float4 s2 = *(const float4*)(g_part[2] + off);
            float4 s3 = *(const float4*)(g_part[3] + off);
            const float* xp = g_xp + ((size_t)row * SEQ + t) * NDIM + col;
            float4 x4 = *(const float4*)xp;
            float4 o;
            o.x = tanhf(s0.x + s1.x + s2.x + s3.x + x4.x);
            o.y = tanhf(s0.y + s1.y + s2.y + s3.y + x4.y);
            o.z = tanhf(s0.z + s1.z + s2.z + s3.z + x4.z);
            o.w = tanhf(s0.w + s1.w + s2.w + s3.w + x4.w);
            *(float4*)(Hout + off) = o;
        }
        if (tid == 0) g_cnt[tile] = 0;   // reset for next step / next replay
    }
}

// ---------------------------------------------------------------------------
// Final: out = h_final @ W_hy + b_y   (h_final lives in g_h[0] after 512 steps)
// ---------------------------------------------------------------------------
__global__ void __launch_bounds__(128) rnn_final(const float* __restrict__ W,
                                                 const float* __restrict__ bias,
                                                 float* __restrict__ out) {
    __shared__ float As[32 * 34];
    __shared__ float Bs[32 * 32];

    const float* __restrict__ H = g_h[0];

    const int tid = threadIdx.x;
    const int bx  = blockIdx.x;
    const int by  = blockIdx.y;

    const int rI = tid / 8;
    const int cI = (tid % 8) * 4;
    const int tr = tid / 8;
    const int tc = tid % 8;

    float acc[2][4];
#pragma unroll
    for (int i = 0; i < 2; i++)
#pragma unroll
        for (int j = 0; j < 4; j++) acc[i][j] = 0.0f;

    for (int bk = 0; bk < NDIM; bk += 32) {
#pragma unroll
        for (int rr = 0; rr < 2; rr++) {
            int r = rI + rr * 16;
            float4 a = *(const float4*)(H + (by * 32 + r) * NDIM + bk + cI);
            As[(cI + 0) * 34 + r] = a.x;
            As[(cI + 1) * 34 + r] = a.y;
            As[(cI + 2) * 34 + r] = a.z;
            As[(cI + 3) * 34 + r] = a.w;
            *(float4*)(Bs + r * 32 + cI) =
                *(const float4*)(W + (size_t)(bk + r) * NDIM + bx * 32 + cI);
        }
        __syncthreads();

#pragma unroll
        for (int k = 0; k < 32; k++) {
            float2 av = *(const float2*)(As + k * 34 + tr * 2);
            float4 bv = *(const float4*)(Bs + k * 32 + tc * 4);
            acc[0][0] += av.x * bv.x; acc[0][1] += av.x * bv.y;
            acc[0][2] += av.x * bv.z; acc[0][3] += av.x * bv.w;
            acc[1][0] += av.y * bv.x; acc[1][1] += av.y * bv.y;
            acc[1][2] += av.y * bv.z; acc[1][3] += av.y * bv.w;
        }
        __syncthreads();
    }

    const int col = bx * 32 + tc * 4;
    float4 bv4 = *(const float4*)(bias + col);
#pragma unroll
    for (int i = 0; i < 2; i++) {
        int row = by * 32 + tr * 2 + i;
        float4 v;
        v.x = acc[i][0] + bv4.x;
        v.y = acc[i][1] + bv4.y;
        v.z = acc[i][2] + bv4.z;
        v.w = acc[i][3] + bv4.w;
        *(float4*)(out + row * NDIM + col) = v;
    }
}

// ---------------------------------------------------------------------------
// kernel_launch — graph-capturable: kernel launches only
// ---------------------------------------------------------------------------
extern "C" void kernel_launch(void* const* d_in, const int* in_sizes, int n_in,
                              void* d_out, int out_size) {
    (void)in_sizes; (void)n_in; (void)out_size;
    const float* x    = (const float*)d_in[0];
    const float* W_xh = (const float*)d_in[1];
    const float* W_hh = (const float*)d_in[2];
    const float* b_h  = (const float*)d_in[3];
    const float* W_hy = (const float*)d_in[4];
    const float* b_y  = (const float*)d_in[5];
    float* out = (float*)d_out;

    zero_h0<<<(BATCH * NDIM + 511) / 512, 512>>>();

    dim3 gridXP(NDIM / 128, (BATCH * SEQ) / 128);   // (8, 512)
    xp_gemm<<<gridXP, 256>>>(x, W_xh, b_h);

    dim3 gridStep(NDIM / 64, BATCH / 64, SPLITK);   // (16, 2, 4) = 128 CTAs
    for (int t = 0; t < SEQ; t++) {
        rnn_step<<<gridStep, 256>>>(W_hh, t);
    }

    dim3 gridFin(NDIM / 32, BATCH / 32);            // (32, 4)
    rnn_final<<<gridFin, 128>>>(W_hy, b_y, out);
}

// round 4
// speedup vs baseline: 2.0645x; 1.3260x over previous
#include <cuda_runtime.h>
#include <cuda_bf16.h>
#include <math.h>
#include <stdint.h>

#define BATCH 128
#define SEQ   512
#define NDIM  1024
#define NKC   8            // recurrence k-chunks (K=1024 / 128)
#define NJT   16           // recurrence n-tiles (N=1024 / 64)
#define RGRID (NKC * NJT)  // 128 persistent CTAs

// ---------------------------------------------------------------------------
// Global scratch (allocation-free)
// ---------------------------------------------------------------------------
__device__ float g_xp[(size_t)BATCH * SEQ * NDIM];        // 256 MB
__device__ __nv_bfloat16 g_Wt_hi[(size_t)NDIM * NDIM];    // W_xh^T hi  [N][K]
__device__ __nv_bfloat16 g_Wt_lo[(size_t)NDIM * NDIM];
__device__ __nv_bfloat16 g_Whh_hi[(size_t)NDIM * NDIM];   // W_hh^T hi  [N][K]
__device__ __nv_bfloat16 g_Whh_lo[(size_t)NDIM * NDIM];
__device__ __nv_bfloat16 g_hbf_hi[BATCH * NDIM];          // h split hi
__device__ __nv_bfloat16 g_hbf_lo[BATCH * NDIM];
__device__ float g_part2[NKC * NJT * BATCH * 64];         // [c][j][m][nl] 4 MB
__device__ float g_hfin[BATCH * NDIM];                    // final h fp32
__device__ unsigned g_cnt2;                               // barrier counter
__device__ volatile unsigned g_gen;                       // barrier generation

// ---------------------------------------------------------------------------
// Helpers
// ---------------------------------------------------------------------------
__device__ __forceinline__ uint32_t smem_u32(const void* p) {
    uint32_t a;
    asm("{ .reg .u64 t; cvta.to.shared.u64 t, %1; cvt.u32.u64 %0, t; }"
        : "=r"(a) : "l"(p));
    return a;
}

__device__ __forceinline__ void ldsm4(uint32_t (&r)[4], uint32_t addr) {
    asm volatile("ldmatrix.sync.aligned.m8n8.x4.shared.b16 {%0,%1,%2,%3}, [%4];"
                 : "=r"(r[0]), "=r"(r[1]), "=r"(r[2]), "=r"(r[3]) : "r"(addr));
}

__device__ __forceinline__ void mma_bf16(float (&d)[4], const uint32_t (&a)[4],
                                         const uint32_t b0, const uint32_t b1) {
    asm volatile(
        "mma.sync.aligned.m16n8k16.row.col.f32.bf16.bf16.f32 "
        "{%0,%1,%2,%3}, {%4,%5,%6,%7}, {%8,%9}, {%0,%1,%2,%3};"
        : "+f"(d[0]), "+f"(d[1]), "+f"(d[2]), "+f"(d[3])
        : "r"(a[0]), "r"(a[1]), "r"(a[2]), "r"(a[3]), "r"(b0), "r"(b1));
}

// split 8 fp32 -> 8 bf16 hi + 8 bf16 lo (packed uint4 each)
__device__ __forceinline__ void split8(float4 f0, float4 f1, uint4& hi, uint4& lo) {
    float f[8] = {f0.x, f0.y, f0.z, f0.w, f1.x, f1.y, f1.z, f1.w};
    unsigned short h[8], l[8];
#pragma unroll
    for (int i = 0; i < 8; i++) {
        __nv_bfloat16 bh = __float2bfloat16_rn(f[i]);
        float r = f[i] - __bfloat162float(bh);
        h[i] = __bfloat16_as_ushort(bh);
        l[i] = __bfloat16_as_ushort(__float2bfloat16_rn(r));
    }
    hi.x = (uint32_t)h[0] | ((uint32_t)h[1] << 16);
    hi.y = (uint32_t)h[2] | ((uint32_t)h[3] << 16);
    hi.z = (uint32_t)h[4] | ((uint32_t)h[5] << 16);
    hi.w = (uint32_t)h[6] | ((uint32_t)h[7] << 16);
    lo.x = (uint32_t)l[0] | ((uint32_t)l[1] << 16);
    lo.y = (uint32_t)l[2] | ((uint32_t)l[3] << 16);
    lo.z = (uint32_t)l[4] | ((uint32_t)l[5] << 16);
    lo.w = (uint32_t)l[6] | ((uint32_t)l[7] << 16);
}

__device__ __forceinline__ void grid_barrier() {
    __syncthreads();
    if (threadIdx.x == 0) {
        unsigned gen = g_gen;
        __threadfence();
        if (atomicAdd(&g_cnt2, 1) == RGRID - 1) {
            atomicExch(&g_cnt2, 0);
            __threadfence();
            atomicAdd((unsigned*)&g_gen, 1);
        } else {
            while (g_gen == gen) __nanosleep(40);
        }
    }
    __syncthreads();
}

// ---------------------------------------------------------------------------
// Small setup kernels
// ---------------------------------------------------------------------------
__global__ void zero_hbf() {
    int idx = blockIdx.x * blockDim.x + threadIdx.x;
    if (idx < BATCH * NDIM) {
        g_hbf_hi[idx] = __float2bfloat16_rn(0.0f);
        g_hbf_lo[idx] = __float2bfloat16_rn(0.0f);
    }
}

// Transpose + split W [K,N] -> dst_hi/lo [N,K] bf16.  which: 0 = W_xh, 1 = W_hh
__global__ void wprep(const float* __restrict__ W, int which) {
    __shared__ float t[32][33];
    __nv_bfloat16* dhi = which ? g_Whh_hi : g_Wt_hi;
    __nv_bfloat16* dlo = which ? g_Whh_lo : g_Wt_lo;
    int tx = threadIdx.x, ty = threadIdx.y;
    int nb = blockIdx.x * 32, kb = blockIdx.y * 32;
#pragma unroll
    for (int i = ty; i < 32; i += 8)
        t[i][tx] = W[(size_t)(kb + i) * NDIM + nb + tx];
    __syncthreads();
#pragma unroll
    for (int i = ty; i < 32; i += 8) {
        float f = t[tx][i];                       // W[kb+tx][nb+i]
        __nv_bfloat16 bh = __float2bfloat16_rn(f);
        float r = f - __bfloat162float(bh);
        size_t off = (size_t)(nb + i) * NDIM + kb + tx;
        dhi[off] = bh;
        dlo[off] = __float2bfloat16_rn(r);
    }
}

// ---------------------------------------------------------------------------
// XP GEMM via mma.sync bf16-split: g_xp = x @ W_xh + b_h
// CTA 128x128, 8 warps (2Mx4N -> 64x32), K-chunk 32, double-buffered smem.
// smem rows padded to 40 bf16 (80B) for conflict-free ldmatrix.
// ---------------------------------------------------------------------------
#define XP_ARR  10240            // 128 rows * 80 B
#define XP_BUF  (4 * XP_ARR)     // A_hi, A_lo, B_hi, B_lo
#define XP_SMEM (2 * XP_BUF)     // 81920

__global__ void __launch_bounds__(256) xp_gemm_mma(const float* __restrict__ A,
                                                   const float* __restrict__ bias) {
    extern __shared__ __align__(16) unsigned char sm[];
    const uint32_t sb = smem_u32(sm);
    const int tid = threadIdx.x, wid = tid >> 5, lane = tid & 31;
    const int cCol = blockIdx.x, cRow = blockIdx.y;
    const int wm = (wid >> 2) * 64;
    const int wn = (wid & 3) * 32;

    const int lrow = tid >> 1;
    const int lhf  = tid & 1;
    const float* Ag = A + (size_t)(cRow * 128 + lrow) * NDIM + lhf * 16;
    const __nv_bfloat16* Bhg = g_Wt_hi + (size_t)(cCol * 128 + lrow) * NDIM + lhf * 16;
    const __nv_bfloat16* Blg = g_Wt_lo + (size_t)(cCol * 128 + lrow) * NDIM + lhf * 16;
    unsigned char* st_a = sm + lrow * 80 + lhf * 32;   // + buf*XP_BUF (+16 for j=1)
    unsigned char* st_b = sm + 2 * XP_ARR + lrow * 80 + lhf * 32;

    float acc[4][4][4];
#pragma unroll
    for (int i = 0; i < 4; i++)
#pragma unroll
        for (int j = 0; j < 4; j++)
#pragma unroll
            for (int q = 0; q < 4; q++) acc[i][j][q] = 0.0f;

    // prologue: chunk 0 -> buf 0
    {
        float4 f0 = *(const float4*)(Ag + 0);
        float4 f1 = *(const float4*)(Ag + 4);
        float4 f2 = *(const float4*)(Ag + 8);
        float4 f3 = *(const float4*)(Ag + 12);
        uint4 h0, l0, h1, l1;
        split8(f0, f1, h0, l0);
        split8(f2, f3, h1, l1);
        *(uint4*)(st_a +  0) = h0; *(uint4*)(st_a + 16) = h1;
        *(uint4*)(st_a + XP_ARR +  0) = l0; *(uint4*)(st_a + XP_ARR + 16) = l1;
        uint4 bh0 = *(const uint4*)(Bhg);     uint4 bh1 = *(const uint4*)(Bhg + 8);
        uint4 bl0 = *(const uint4*)(Blg);     uint4 bl1 = *(const uint4*)(Blg + 8);
        *(uint4*)(st_b +  0) = bh0; *(uint4*)(st_b + 16) = bh1;
        *(uint4*)(st_b + XP_ARR +  0) = bl0; *(uint4*)(st_b + XP_ARR + 16) = bl1;
    }
    __syncthreads();

#pragma unroll 1
    for (int ko = 0; ko < 32; ko++) {
        const int buf = ko & 1;
        float4 f0, f1, f2, f3;
        uint4 pbh0, pbh1, pbl0, pbl1;
        if (ko < 31) {
            const float* Ap = Ag + (ko + 1) * 32;
            f0 = *(const float4*)(Ap + 0);  f1 = *(const float4*)(Ap + 4);
            f2 = *(const float4*)(Ap + 8);  f3 = *(const float4*)(Ap + 12);
            pbh0 = *(const uint4*)(Bhg + (ko + 1) * 32);
            pbh1 = *(const uint4*)(Bhg + (ko + 1) * 32 + 8);
            pbl0 = *(const uint4*)(Blg + (ko + 1) * 32);
            pbl1 = *(const uint4*)(Blg + (ko + 1) * 32 + 8);
        }

        const uint32_t base = sb + buf * XP_BUF;
#pragma unroll
        for (int s = 0; s < 2; s++) {
            const uint32_t k0b = s * 32;
            uint32_t ah[4][4], al[4][4];
#pragma unroll
            for (int mi = 0; mi < 4; mi++) {
                uint32_t ad = base + (wm + mi * 16 + (lane & 15)) * 80 + k0b + (lane >> 4) * 16;
                ldsm4(ah[mi], ad);
                ldsm4(al[mi], ad + XP_ARR);
            }
            uint32_t bh[4][2], bl[4][2];
#pragma unroll
            for (int nb = 0; nb < 2; nb++) {
                uint32_t bd = base + 2 * XP_ARR +
                              (wn + nb * 16 + (lane & 7) + ((lane >> 4) << 3)) * 80 +
                              k0b + (((lane >> 3) & 1) << 4);
                uint32_t r[4];
                ldsm4(r, bd);
                bh[nb * 2 + 0][0] = r[0]; bh[nb * 2 + 0][1] = r[1];
                bh[nb * 2 + 1][0] = r[2]; bh[nb * 2 + 1][1] = r[3];
                ldsm4(r, bd + XP_ARR);
                bl[nb * 2 + 0][0] = r[0]; bl[nb * 2 + 0][1] = r[1];
                bl[nb * 2 + 1][0] = r[2]; bl[nb * 2 + 1][1] = r[3];
            }
#pragma unroll
            for (int mi = 0; mi < 4; mi++)
#pragma unroll
                for (int nj = 0; nj < 4; nj++) {
                    mma_bf16(acc[mi][nj], ah[mi], bh[nj][0], bh[nj][1]);
                    mma_bf16(acc[mi][nj], ah[mi], bl[nj][0], bl[nj][1]);
                    mma_bf16(acc[mi][nj], al[mi], bh[nj][0], bh[nj][1]);
                }
        }

        if (ko < 31) {
            unsigned char* da = st_a + (buf ^ 1) * XP_BUF;
            unsigned char* db = st_b + (buf ^ 1) * XP_BUF;
            uint4 h0, l0, h1, l1;
            split8(f0, f1, h0, l0);
            split8(f2, f3, h1, l1);
            *(uint4*)(da +  0) = h0; *(uint4*)(da + 16) = h1;
            *(uint4*)(da + XP_ARR +  0) = l0; *(uint4*)(da + XP_ARR + 16) = l1;
            *(uint4*)(db +  0) = pbh0; *(uint4*)(db + 16) = pbh1;
            *(uint4*)(db + XP_ARR +  0) = pbl0; *(uint4*)(db + XP_ARR + 16) = pbl1;
            __syncthreads();
        }
    }

    // epilogue: write fp32 + bias
#pragma unroll
    for (int mi = 0; mi < 4; mi++) {
        int row = cRow * 128 + wm + mi * 16 + (lane >> 2);
#pragma unroll
        for (int nj = 0; nj < 4; nj++) {
            int col = cCol * 128 + wn + nj * 8 + (lane & 3) * 2;
            float b0 = bias[col], b1 = bias[col + 1];
            float2 v0 = {acc[mi][nj][0] + b0, acc[mi][nj][1] + b1};
            float2 v1 = {acc[mi][nj][2] + b0, acc[mi][nj][3] + b1};
            *(float2*)(g_xp + (size_t)row * NDIM + col) = v0;
            *(float2*)(g_xp + (size_t)(row + 8) * NDIM + col) = v1;
        }
    }
}

// ---------------------------------------------------------------------------
// Persistent recurrence: 128 CTAs, each owns (n-tile j of 64, k-chunk c of 128).
// W_hh chunk stays in SMEM for all 512 steps. Per step:
//   A: load h (bf16 hi/lo) cols [128c,+128) -> smem, HMMA 128x64 partial -> gmem
//   barrier; B: CTA r reduces row m=r over 8 chunks + xp + tanh -> h hi/lo
//   barrier; repeat.
// smem rows padded to 136 bf16 (272B).
// ---------------------------------------------------------------------------
#define RS        272
#define R_AHI     0
#define R_ALO     34816              // 128*272
#define R_WHI     69632
#define R_WLO     87040              // +64*272
#define R_SMEM    104448

__global__ void __launch_bounds__(256) rnn_persistent() {
    extern __shared__ __align__(16) unsigned char sm[];
    const uint32_t sb = smem_u32(sm);
    const int tid = threadIdx.x, wid = tid >> 5, lane = tid & 31;
    const int r = blockIdx.x;
    const int j = r & 15;          // n-tile
    const int c = r >> 4;          // k-chunk
    const int wm = (wid >> 1) * 32;
    const int wn = (wid & 1) * 32;

    // ---- load W_hh chunk into smem (persistent) ----
    {
        const int wrow = tid >> 2;             // 0..63
        const int seg  = (tid & 3) * 32;       // k offset (bf16)
        const __nv_bfloat16* gh = g_Whh_hi + (size_t)(j * 64 + wrow) * NDIM + c * 128 + seg;
        const __nv_bfloat16* gl = g_Whh_lo + (size_t)(j * 64 + wrow) * NDIM + c * 128 + seg;
        unsigned char* dh = sm + R_WHI + wrow * RS + seg * 2;
        unsigned char* dl = sm + R_WLO + wrow * RS + seg * 2;
#pragma unroll
        for (int i = 0; i < 4; i++) {
            *(uint4*)(dh + i * 16) = *(const uint4*)((const unsigned char*)gh + i * 16);
            *(uint4*)(dl + i * 16) = *(const uint4*)((const unsigned char*)gl + i * 16);
        }
    }

    const int m_l  = tid >> 1;                 // h-load row
    const int hf_l = (tid & 1) * 64;           // h-load col half (elems)
    const __nv_bfloat16* HgH = g_hbf_hi + (size_t)m_l * NDIM + c * 128 + hf_l;
    const __nv_bfloat16* HgL = g_hbf_lo + (size_t)m_l * NDIM + c * 128 + hf_l;
    unsigned char* AdH = sm + R_AHI + m_l * RS + hf_l * 2;
    unsigned char* AdL = sm + R_ALO + m_l * RS + hf_l * 2;

    const int colB = tid * 4;                  // phase-B columns (4 per thread)
    const int jjB = colB >> 6, nlB = colB & 63;
    const int mB = r;

#pragma unroll 1
    for (int t = 0; t < SEQ; t++) {
        // prefetch xp for phase B (DRAM latency hidden behind phase A)
        float4 xpv = *(const float4*)(g_xp + ((size_t)mB * SEQ + t) * NDIM + colB);

        // ---- phase A: load h chunk into smem ----
#pragma unroll
        for (int i = 0; i < 8; i++) {
            *(uint4*)(AdH + i * 16) = *(const uint4*)((const unsigned char*)HgH + i * 16);
            *(uint4*)(AdL + i * 16) = *(const uint4*)((const unsigned char*)HgL + i * 16);
        }
        __syncthreads();

        float acc[2][4][4];
#pragma unroll
        for (int mi = 0; mi < 2; mi++)
#pragma unroll
            for (int nj = 0; nj < 4; nj++)
#pragma unroll
                for (int q = 0; q < 4; q++) acc[mi][nj][q] = 0.0f;

#pragma unroll
        for (int ks = 0; ks < 8; ks++) {
            const uint32_t k0b = ks * 32;
            uint32_t ah[2][4], al[2][4];
#pragma unroll
            for (int mi = 0; mi < 2; mi++) {
                uint32_t ad = sb + R_AHI + (wm + mi * 16 + (lane & 15)) * RS + k0b + (lane >> 4) * 16;
                ldsm4(ah[mi], ad);
                ldsm4(al[mi], ad + (R_ALO - R_AHI));
            }
            uint32_t bh[4][2], bl[4][2];
#pragma unroll
            for (int nb = 0; nb < 2; nb++) {
                uint32_t bd = sb + R_WHI +
                              (wn + nb * 16 + (lane & 7) + ((lane >> 4) << 3)) * RS +
                              k0b + (((lane >> 3) & 1) << 4);
                uint32_t rr[4];
                ldsm4(rr, bd);
                bh[nb * 2 + 0][0] = rr[0]; bh[nb * 2 + 0][1] = rr[1];
                bh[nb * 2 + 1][0] = rr[2]; bh[nb * 2 + 1][1] = rr[3];
                ldsm4(rr, bd + (R_WLO - R_WHI));
                bl[nb * 2 + 0][0] = rr[0]; bl[nb * 2 + 0][1] = rr[1];
                bl[nb * 2 + 1][0] = rr[2]; bl[nb * 2 + 1][1] = rr[3];
            }
#pragma unroll
            for (int mi = 0; mi < 2; mi++)
#pragma unroll
                for (int nj = 0; nj < 4; nj++) {
                    mma_bf16(acc[mi][nj], ah[mi], bh[nj][0], bh[nj][1]);
                    mma_bf16(acc[mi][nj], ah[mi], bl[nj][0], bl[nj][1]);
                    mma_bf16(acc[mi][nj], al[mi], bh[nj][0], bh[nj][1]);
                }
        }
        __syncthreads();   // smem A reuse next step guarded by barriers below

        // write partials
#pragma unroll
        for (int mi = 0; mi < 2; mi++) {
            int row = wm + mi * 16 + (lane >> 2);
#pragma unroll
            for (int nj = 0; nj < 4; nj++) {
                int nl = wn + nj * 8 + (lane & 3) * 2;
                size_t idx = ((size_t)(c * 16 + j) * 128 + row) * 64 + nl;
                *(float2*)(g_part2 + idx) = make_float2(acc[mi][nj][0], acc[mi][nj][1]);
                *(float2*)(g_part2 + idx + 8 * 64) = make_float2(acc[mi][nj][2], acc[mi][nj][3]);
            }
        }
        __threadfence();
        grid_barrier();

        // ---- phase B: reduce row m = r, cols [colB, colB+4) ----
        float4 s = make_float4(0.f, 0.f, 0.f, 0.f);
#pragma unroll
        for (int cc = 0; cc < NKC; cc++) {
            const float4 p = *(const float4*)(g_part2 +
                ((size_t)(cc * 16 + jjB) * 128 + mB) * 64 + nlB);
            s.x += p.x; s.y += p.y; s.z += p.z; s.w += p.w;
        }
        float h0 = tanhf(s.x + xpv.x);
        float h1 = tanhf(s.y + xpv.y);
        float h2 = tanhf(s.z + xpv.z);
        float h3 = tanhf(s.w + xpv.w);

        uint4 hi, lo;
        split8(make_float4(h0, h1, h2, h3), make_float4(0.f, 0.f, 0.f, 0.f), hi, lo);
        *(uint2*)(g_hbf_hi + (size_t)mB * NDIM + colB) = make_uint2(hi.x, hi.y);
        *(uint2*)(g_hbf_lo + (size_t)mB * NDIM + colB) = make_uint2(lo.x, lo.y);
        if (t == SEQ - 1)
            *(float4*)(g_hfin + (size_t)mB * NDIM + colB) = make_float4(h0, h1, h2, h3);

        __threadfence();
        grid_barrier();
    }
}

// ---------------------------------------------------------------------------
// Final: out = h_final @ W_hy + b_y (fp32 FFMA; single small launch)
// ---------------------------------------------------------------------------
__global__ void __launch_bounds__(128) rnn_final(const float* __restrict__ W,
                                                 const float* __restrict__ bias,
                                                 float* __restrict__ out) {
    __shared__ float As[32 * 34];
    __shared__ float Bs[32 * 32];

    const float* __restrict__ H = g_hfin;

    const int tid = threadIdx.x;
    const int bx  = blockIdx.x;
    const int by  = blockIdx.y;

    const int rI = tid / 8;
    const int cI = (tid % 8) * 4;
    const int tr = tid / 8;
    const int tc = tid % 8;

    float acc[2][4];
#pragma unroll
    for (int i = 0; i < 2; i++)
#pragma unroll
        for (int q = 0; q < 4; q++) acc[i][q] = 0.0f;

    for (int bk = 0; bk < NDIM; bk += 32) {
#pragma unroll
        for (int rr = 0; rr < 2; rr++) {
            int rw = rI + rr * 16;
            float4 a = *(const float4*)(H + (by * 32 + rw) * NDIM + bk + cI);
            As[(cI + 0) * 34 + rw] = a.x;
            As[(cI + 1) * 34 + rw] = a.y;
            As[(cI + 2) * 34 + rw] = a.z;
            As[(cI + 3) * 34 + rw] = a.w;
            *(float4*)(Bs + rw * 32 + cI) =
                *(const float4*)(W + (size_t)(bk + rw) * NDIM + bx * 32 + cI);
        }
        __syncthreads();

#pragma unroll
        for (int k = 0; k < 32; k++) {
            float2 av = *(const float2*)(As + k * 34 + tr * 2);
            float4 bv = *(const float4*)(Bs + k * 32 + tc * 4);
            acc[0][0] += av.x * bv.x; acc[0][1] += av.x * bv.y;
            acc[0][2] += av.x * bv.z; acc[0][3] += av.x * bv.w;
            acc[1][0] += av.y * bv.x; acc[1][1] += av.y * bv.y;
            acc[1][2] += av.y * bv.z; acc[1][3] += av.y * bv.w;
        }
        __syncthreads();
    }

    const int col = bx * 32 + tc * 4;
    float4 bv4 = *(const float4*)(bias + col);
#pragma unroll
    for (int i = 0; i < 2; i++) {
        int row = by * 32 + tr * 2 + i;
        float4 v;
        v.x = acc[i][0] + bv4.x;
        v.y = acc[i][1] + bv4.y;
        v.z = acc[i][2] + bv4.z;
        v.w = acc[i][3] + bv4.w;
        *(float4*)(out + row * NDIM + col) = v;
    }
}

// ---------------------------------------------------------------------------
// kernel_launch — graph-capturable (kernel launches only)
// ---------------------------------------------------------------------------
extern "C" void kernel_launch(void* const* d_in, const int* in_sizes, int n_in,
                              void* d_out, int out_size) {
    (void)in_sizes; (void)n_in; (void)out_size;
    const float* x    = (const float*)d_in[0];
    const float* W_xh = (const float*)d_in[1];
    const float* W_hh = (const float*)d_in[2];
    const float* b_h  = (const float*)d_in[3];
    const float* W_hy = (const float*)d_in[4];
    const float* b_y  = (const float*)d_in[5];
    float* out = (float*)d_out;

    cudaFuncSetAttribute(xp_gemm_mma, cudaFuncAttributeMaxDynamicSharedMemorySize, XP_SMEM);
    cudaFuncSetAttribute(rnn_persistent, cudaFuncAttributeMaxDynamicSharedMemorySize, R_SMEM);

    zero_hbf<<<(BATCH * NDIM + 511) / 512, 512>>>();

    dim3 gridW(NDIM / 32, NDIM / 32);
    wprep<<<gridW, dim3(32, 8)>>>(W_xh, 0);
    wprep<<<gridW, dim3(32, 8)>>>(W_hh, 1);

    dim3 gridXP(NDIM / 128, (BATCH * SEQ) / 128);   // (8, 512)
    xp_gemm_mma<<<gridXP, 256, XP_SMEM>>>(x, b_h);

    rnn_persistent<<<RGRID, 256, R_SMEM>>>();

    dim3 gridFin(NDIM / 32, BATCH / 32);
    rnn_final<<<gridFin, 128>>>(W_hy, b_y, out);
}

// round 5
// speedup vs baseline: 2.8289x; 1.3702x over previous
#include <cuda_runtime.h>
#include <cuda_bf16.h>
#include <math.h>
#include <stdint.h>

#define BATCH 128
#define SEQ   512
#define NDIM  1024
#define RGRID 128          // persistent CTAs: 4 m-blocks x 32 n-blocks

// ---------------------------------------------------------------------------
// Global scratch (allocation-free)
// ---------------------------------------------------------------------------
__device__ float g_xp[(size_t)BATCH * SEQ * NDIM];        // 256 MB
__device__ __nv_bfloat16 g_Wt_hi[(size_t)NDIM * NDIM];    // W_xh^T hi  [N][K]
__device__ __nv_bfloat16 g_Wt_lo[(size_t)NDIM * NDIM];
__device__ __nv_bfloat16 g_Whh_hi[(size_t)NDIM * NDIM];   // W_hh^T hi  [N][K]
__device__ __nv_bfloat16 g_Whh_lo[(size_t)NDIM * NDIM];
__device__ __nv_bfloat16 g_hbf_hi[2][BATCH * NDIM];       // ping-pong h hi
__device__ __nv_bfloat16 g_hbf_lo[2][BATCH * NDIM];       // ping-pong h lo
__device__ float g_hfin[BATCH * NDIM];                    // final h fp32
__device__ unsigned g_cnt2;                               // barrier counter
__device__ volatile unsigned g_gen;                       // barrier generation

// ---------------------------------------------------------------------------
// Helpers
// ---------------------------------------------------------------------------
__device__ __forceinline__ uint32_t smem_u32(const void* p) {
    uint32_t a;
    asm("{ .reg .u64 t; cvta.to.shared.u64 t, %1; cvt.u32.u64 %0, t; }"
        : "=r"(a) : "l"(p));
    return a;
}

__device__ __forceinline__ void ldsm4(uint32_t (&r)[4], uint32_t addr) {
    asm volatile("ldmatrix.sync.aligned.m8n8.x4.shared.b16 {%0,%1,%2,%3}, [%4];"
                 : "=r"(r[0]), "=r"(r[1]), "=r"(r[2]), "=r"(r[3]) : "r"(addr));
}

__device__ __forceinline__ void mma_bf16(float (&d)[4], const uint32_t (&a)[4],
                                         const uint32_t b0, const uint32_t b1) {
    asm volatile(
        "mma.sync.aligned.m16n8k16.row.col.f32.bf16.bf16.f32 "
        "{%0,%1,%2,%3}, {%4,%5,%6,%7}, {%8,%9}, {%0,%1,%2,%3};"
        : "+f"(d[0]), "+f"(d[1]), "+f"(d[2]), "+f"(d[3])
        : "r"(a[0]), "r"(a[1]), "r"(a[2]), "r"(a[3]), "r"(b0), "r"(b1));
}

// split 8 fp32 -> 8 bf16 hi + 8 bf16 lo (packed uint4 each)
__device__ __forceinline__ void split8(float4 f0, float4 f1, uint4& hi, uint4& lo) {
    float f[8] = {f0.x, f0.y, f0.z, f0.w, f1.x, f1.y, f1.z, f1.w};
    unsigned short h[8], l[8];
#pragma unroll
    for (int i = 0; i < 8; i++) {
        __nv_bfloat16 bh = __float2bfloat16_rn(f[i]);
        float r = f[i] - __bfloat162float(bh);
        h[i] = __bfloat16_as_ushort(bh);
        l[i] = __bfloat16_as_ushort(__float2bfloat16_rn(r));
    }
    hi.x = (uint32_t)h[0] | ((uint32_t)h[1] << 16);
    hi.y = (uint32_t)h[2] | ((uint32_t)h[3] << 16);
    hi.z = (uint32_t)h[4] | ((uint32_t)h[5] << 16);
    hi.w = (uint32_t)h[6] | ((uint32_t)h[7] << 16);
    lo.x = (uint32_t)l[0] | ((uint32_t)l[1] << 16);
    lo.y = (uint32_t)l[2] | ((uint32_t)l[3] << 16);
    lo.z = (uint32_t)l[4] | ((uint32_t)l[5] << 16);
    lo.w = (uint32_t)l[6] | ((uint32_t)l[7] << 16);
}

// split 2 fp32 -> packed bf16x2 hi + lo
__device__ __forceinline__ void split2(float a, float b, uint32_t& hi, uint32_t& lo) {
    __nv_bfloat16 ah = __float2bfloat16_rn(a), bh = __float2bfloat16_rn(b);
    float ar = a - __bfloat162float(ah), br = b - __bfloat162float(bh);
    hi = (uint32_t)__bfloat16_as_ushort(ah) |
         ((uint32_t)__bfloat16_as_ushort(bh) << 16);
    lo = (uint32_t)__bfloat16_as_ushort(__float2bfloat16_rn(ar)) |
         ((uint32_t)__bfloat16_as_ushort(__float2bfloat16_rn(br)) << 16);
}

__device__ __forceinline__ void grid_barrier() {
    __syncthreads();
    if (threadIdx.x == 0) {
        unsigned gen = g_gen;
        __threadfence();
        if (atomicAdd(&g_cnt2, 1) == RGRID - 1) {
            atomicExch(&g_cnt2, 0);
            __threadfence();
            atomicAdd((unsigned*)&g_gen, 1);
        } else {
            while (g_gen == gen) __nanosleep(20);
            __threadfence();
        }
    }
    __syncthreads();
}

// ---------------------------------------------------------------------------
// Setup kernels
// ---------------------------------------------------------------------------
__global__ void zero_hbf() {
    int idx = blockIdx.x * blockDim.x + threadIdx.x;
    if (idx < BATCH * NDIM) {
        g_hbf_hi[0][idx] = __float2bfloat16_rn(0.0f);
        g_hbf_lo[0][idx] = __float2bfloat16_rn(0.0f);
    }
}

// Transpose + split W [K,N] -> dst_hi/lo [N,K] bf16.  which: 0 = W_xh, 1 = W_hh
__global__ void wprep(const float* __restrict__ W, int which) {
    __shared__ float t[32][33];
    __nv_bfloat16* dhi = which ? g_Whh_hi : g_Wt_hi;
    __nv_bfloat16* dlo = which ? g_Whh_lo : g_Wt_lo;
    int tx = threadIdx.x, ty = threadIdx.y;
    int nb = blockIdx.x * 32, kb = blockIdx.y * 32;
#pragma unroll
    for (int i = ty; i < 32; i += 8)
        t[i][tx] = W[(size_t)(kb + i) * NDIM + nb + tx];
    __syncthreads();
#pragma unroll
    for (int i = ty; i < 32; i += 8) {
        float f = t[tx][i];
        __nv_bfloat16 bh = __float2bfloat16_rn(f);
        float r = f - __bfloat162float(bh);
        size_t off = (size_t)(nb + i) * NDIM + kb + tx;
        dhi[off] = bh;
        dlo[off] = __float2bfloat16_rn(r);
    }
}

// ---------------------------------------------------------------------------
// XP GEMM via mma.sync bf16-split (unchanged from round 4 — tensor 45%)
// ---------------------------------------------------------------------------
#define XP_ARR  10240
#define XP_BUF  (4 * XP_ARR)
#define XP_SMEM (2 * XP_BUF)

__global__ void __launch_bounds__(256) xp_gemm_mma(const float* __restrict__ A,
                                                   const float* __restrict__ bias) {
    extern __shared__ __align__(16) unsigned char sm[];
    const uint32_t sb = smem_u32(sm);
    const int tid = threadIdx.x, wid = tid >> 5, lane = tid & 31;
    const int cCol = blockIdx.x, cRow = blockIdx.y;
    const int wm = (wid >> 2) * 64;
    const int wn = (wid & 3) * 32;

    const int lrow = tid >> 1;
    const int lhf  = tid & 1;
    const float* Ag = A + (size_t)(cRow * 128 + lrow) * NDIM + lhf * 16;
    const __nv_bfloat16* Bhg = g_Wt_hi + (size_t)(cCol * 128 + lrow) * NDIM + lhf * 16;
    const __nv_bfloat16* Blg = g_Wt_lo + (size_t)(cCol * 128 + lrow) * NDIM + lhf * 16;
    unsigned char* st_a = sm + lrow * 80 + lhf * 32;
    unsigned char* st_b = sm + 2 * XP_ARR + lrow * 80 + lhf * 32;

    float acc[4][4][4];
#pragma unroll
    for (int i = 0; i < 4; i++)
#pragma unroll
        for (int j = 0; j < 4; j++)
#pragma unroll
            for (int q = 0; q < 4; q++) acc[i][j][q] = 0.0f;

    {
        float4 f0 = *(const float4*)(Ag + 0);
        float4 f1 = *(const float4*)(Ag + 4);
        float4 f2 = *(const float4*)(Ag + 8);
        float4 f3 = *(const float4*)(Ag + 12);
        uint4 h0, l0, h1, l1;
        split8(f0, f1, h0, l0);
        split8(f2, f3, h1, l1);
        *(uint4*)(st_a +  0) = h0; *(uint4*)(st_a + 16) = h1;
        *(uint4*)(st_a + XP_ARR +  0) = l0; *(uint4*)(st_a + XP_ARR + 16) = l1;
        uint4 bh0 = *(const uint4*)(Bhg);     uint4 bh1 = *(const uint4*)(Bhg + 8);
        uint4 bl0 = *(const uint4*)(Blg);     uint4 bl1 = *(const uint4*)(Blg + 8);
        *(uint4*)(st_b +  0) = bh0; *(uint4*)(st_b + 16) = bh1;
        *(uint4*)(st_b + XP_ARR +  0) = bl0; *(uint4*)(st_b + XP_ARR + 16) = bl1;
    }
    __syncthreads();

#pragma unroll 1
    for (int ko = 0; ko < 32; ko++) {
        const int buf = ko & 1;
        float4 f0, f1, f2, f3;
        uint4 pbh0, pbh1, pbl0, pbl1;
        if (ko < 31) {
            const float* Ap = Ag + (ko + 1) * 32;
            f0 = *(const float4*)(Ap + 0);  f1 = *(const float4*)(Ap + 4);
            f2 = *(const float4*)(Ap + 8);  f3 = *(const float4*)(Ap + 12);
            pbh0 = *(const uint4*)(Bhg + (ko + 1) * 32);
            pbh1 = *(const uint4*)(Bhg + (ko + 1) * 32 + 8);
            pbl0 = *(const uint4*)(Blg + (ko + 1) * 32);
            pbl1 = *(const uint4*)(Blg + (ko + 1) * 32 + 8);
        }

        const uint32_t base = sb + buf * XP_BUF;
#pragma unroll
        for (int s = 0; s < 2; s++) {
            const uint32_t k0b = s * 32;
            uint32_t ah[4][4], al[4][4];
#pragma unroll
            for (int mi = 0; mi < 4; mi++) {
                uint32_t ad = base + (wm + mi * 16 + (lane & 15)) * 80 + k0b + (lane >> 4) * 16;
                ldsm4(ah[mi], ad);
                ldsm4(al[mi], ad + XP_ARR);
            }
            uint32_t bh[4][2], bl[4][2];
#pragma unroll
            for (int nb = 0; nb < 2; nb++) {
                uint32_t bd = base + 2 * XP_ARR +
                              (wn + nb * 16 + (lane & 7) + ((lane >> 4) << 3)) * 80 +
                              k0b + (((lane >> 3) & 1) << 4);
                uint32_t r[4];
                ldsm4(r, bd);
                bh[nb * 2 + 0][0] = r[0]; bh[nb * 2 + 0][1] = r[1];
                bh[nb * 2 + 1][0] = r[2]; bh[nb * 2 + 1][1] = r[3];
                ldsm4(r, bd + XP_ARR);
                bl[nb * 2 + 0][0] = r[0]; bl[nb * 2 + 0][1] = r[1];
                bl[nb * 2 + 1][0] = r[2]; bl[nb * 2 + 1][1] = r[3];
            }
#pragma unroll
            for (int mi = 0; mi < 4; mi++)
#pragma unroll
                for (int nj = 0; nj < 4; nj++) {
                    mma_bf16(acc[mi][nj], ah[mi], bh[nj][0], bh[nj][1]);
                    mma_bf16(acc[mi][nj], ah[mi], bl[nj][0], bl[nj][1]);
                    mma_bf16(acc[mi][nj], al[mi], bh[nj][0], bh[nj][1]);
                }
        }

        if (ko < 31) {
            unsigned char* da = st_a + (buf ^ 1) * XP_BUF;
            unsigned char* db = st_b + (buf ^ 1) * XP_BUF;
            uint4 h0, l0, h1, l1;
            split8(f0, f1, h0, l0);
            split8(f2, f3, h1, l1);
            *(uint4*)(da +  0) = h0; *(uint4*)(da + 16) = h1;
            *(uint4*)(da + XP_ARR +  0) = l0; *(uint4*)(da + XP_ARR + 16) = l1;
            *(uint4*)(db +  0) = pbh0; *(uint4*)(db + 16) = pbh1;
            *(uint4*)(db + XP_ARR +  0) = pbl0; *(uint4*)(db + XP_ARR + 16) = pbl1;
            __syncthreads();
        }
    }

#pragma unroll
    for (int mi = 0; mi < 4; mi++) {
        int row = cRow * 128 + wm + mi * 16 + (lane >> 2);
#pragma unroll
        for (int nj = 0; nj < 4; nj++) {
            int col = cCol * 128 + wn + nj * 8 + (lane & 3) * 2;
            float b0 = bias[col], b1 = bias[col + 1];
            float2 v0 = {acc[mi][nj][0] + b0, acc[mi][nj][1] + b1};
            float2 v1 = {acc[mi][nj][2] + b0, acc[mi][nj][3] + b1};
            *(float2*)(g_xp + (size_t)row * NDIM + col) = v0;
            *(float2*)(g_xp + (size_t)(row + 8) * NDIM + col) = v1;
        }
    }
}

// ---------------------------------------------------------------------------
// Persistent recurrence v2: 128 CTAs, each owns a 32x32 output tile, FULL K.
// ONE grid barrier per step, no split-K partials.
// W_hh^T chunk (32 n-rows x 1024 k, hi/lo) persistent in SMEM (139 KB).
// h streamed per 128-k chunk, double-buffered (34 KB).
// 8 warps = (2m x 2n quadrants) x 2 k-halves; k-halves combined via SMEM.
// ---------------------------------------------------------------------------
#define R2_RS    272                 // smem row stride (bytes) for 128 bf16 rows
#define R2_WCH   8704                // 32 * 272 per chunk per array
#define R2_OFFW  0                   // W hi: 8 chunks
#define R2_OFFWL 69632               // W lo: 8 chunks
#define R2_OFFH  139264              // h: 2 bufs x (hi 8704 + lo 8704)
#define R2_HBUF  17408
#define R2_OFFRED R2_OFFH            // reduction area reuses h buf0 (4 KB)
#define R2_SMEM  174080

__global__ void __launch_bounds__(256) rnn_persistent2() {
    extern __shared__ __align__(16) unsigned char sm[];
    const uint32_t sb = smem_u32(sm);
    const int tid = threadIdx.x, wid = tid >> 5, lane = tid & 31;
    const int r  = blockIdx.x;
    const int mi = r >> 5;          // m-block 0..3  (rows mi*32..)
    const int nj = r & 31;          // n-block 0..31 (cols nj*32..)
    const int mq = (wid >> 1) & 1;  // quadrant m
    const int nq = wid & 1;         // quadrant n
    const int kh = wid >> 2;        // k-half 0/1

    // ---- load W_hh^T chunk into smem (once, persistent) ----
    {
        const int n  = tid >> 3;            // 0..31
        const int ko = (tid & 7) * 16;      // k elems
        const __nv_bfloat16* gh = g_Whh_hi + (size_t)(nj * 32 + n) * NDIM + ko;
        const __nv_bfloat16* gl = g_Whh_lo + (size_t)(nj * 32 + n) * NDIM + ko;
        unsigned char* dh = sm + R2_OFFW  + n * R2_RS + ko * 2;
        unsigned char* dl = sm + R2_OFFWL + n * R2_RS + ko * 2;
#pragma unroll
        for (int ks = 0; ks < 8; ks++) {
            *(uint4*)(dh + ks * R2_WCH +  0) = *(const uint4*)((const unsigned char*)(gh + ks * 128));
            *(uint4*)(dh + ks * R2_WCH + 16) = *(const uint4*)((const unsigned char*)(gh + ks * 128) + 16);
            *(uint4*)(dl + ks * R2_WCH +  0) = *(const uint4*)((const unsigned char*)(gl + ks * 128));
            *(uint4*)(dl + ks * R2_WCH + 16) = *(const uint4*)((const unsigned char*)(gl + ks * 128) + 16);
        }
    }

    const int hrow = tid >> 3;              // h loader row 0..31
    const int hko  = (tid & 7) * 16;        // h loader k offset (elems)
    unsigned char* hd_base = sm + R2_OFFH;  // + buf*R2_HBUF; lo at +8704

    // epilogue thread geometry (kh==0 warps)
    const int erow = mi * 32 + mq * 16 + (lane >> 2);
    const int ecol = nj * 32 + nq * 16 + (lane & 3) * 2;

#pragma unroll 1
    for (int t = 0; t < SEQ; t++) {
        const __nv_bfloat16* HgH = g_hbf_hi[t & 1] + (size_t)(mi * 32 + hrow) * NDIM + hko;
        const __nv_bfloat16* HgL = g_hbf_lo[t & 1] + (size_t)(mi * 32 + hrow) * NDIM + hko;

        // xp prefetch (combiner warps only)
        float2 xp00, xp01, xp10, xp11;
        if (kh == 0) {
            const float* b0 = g_xp + ((size_t)erow * SEQ + t) * NDIM;
            const float* b1 = g_xp + ((size_t)(erow + 8) * SEQ + t) * NDIM;
            xp00 = *(const float2*)(b0 + ecol);
            xp01 = *(const float2*)(b0 + ecol + 8);
            xp10 = *(const float2*)(b1 + ecol);
            xp11 = *(const float2*)(b1 + ecol + 8);
        }

        // prologue: h chunk 0 -> buf 0
        {
            unsigned char* dh = hd_base + hrow * R2_RS + hko * 2;
            *(uint4*)(dh +    0 +  0) = *(const uint4*)((const unsigned char*)HgH);
            *(uint4*)(dh +    0 + 16) = *(const uint4*)((const unsigned char*)HgH + 16);
            *(uint4*)(dh + 8704 +  0) = *(const uint4*)((const unsigned char*)HgL);
            *(uint4*)(dh + 8704 + 16) = *(const uint4*)((const unsigned char*)HgL + 16);
        }
        __syncthreads();

        float acc[2][4];
#pragma unroll
        for (int f = 0; f < 2; f++)
#pragma unroll
            for (int q = 0; q < 4; q++) acc[f][q] = 0.0f;

#pragma unroll 1
        for (int ks = 0; ks < 8; ks++) {
            const int buf = ks & 1;

            // prefetch next h chunk to regs
            uint4 ph0, ph1, pl0, pl1;
            if (ks < 7) {
                const unsigned char* sh = (const unsigned char*)(HgH + (ks + 1) * 128);
                const unsigned char* sl = (const unsigned char*)(HgL + (ks + 1) * 128);
                ph0 = *(const uint4*)(sh);      ph1 = *(const uint4*)(sh + 16);
                pl0 = *(const uint4*)(sl);      pl1 = *(const uint4*)(sl + 16);
            }

            const uint32_t hbase = sb + R2_OFFH + buf * R2_HBUF;
            const uint32_t wbase = sb + R2_OFFW + ks * R2_WCH;
#pragma unroll
            for (int kk = 0; kk < 4; kk++) {
                const uint32_t kbyte = kh * 128 + kk * 32;
                uint32_t ah[4], al[4];
                uint32_t ad = hbase + (mq * 16 + (lane & 15)) * R2_RS + kbyte + (lane >> 4) * 16;
                ldsm4(ah, ad);
                ldsm4(al, ad + 8704);

                uint32_t bh[4], bl[4];
                uint32_t bd = wbase + (nq * 16 + (lane & 7) + ((lane >> 4) << 3)) * R2_RS +
                              kbyte + (((lane >> 3) & 1) << 4);
                ldsm4(bh, bd);
                ldsm4(bl, bd + (R2_OFFWL - R2_OFFW));

#pragma unroll
                for (int f = 0; f < 2; f++) {
                    mma_bf16(acc[f], ah, bh[f * 2], bh[f * 2 + 1]);
                    mma_bf16(acc[f], ah, bl[f * 2], bl[f * 2 + 1]);
                    mma_bf16(acc[f], al, bh[f * 2], bh[f * 2 + 1]);
                }
            }

            if (ks < 7) {
                unsigned char* dh = hd_base + (buf ^ 1) * R2_HBUF + hrow * R2_RS + hko * 2;
                *(uint4*)(dh +    0 +  0) = ph0;
                *(uint4*)(dh +    0 + 16) = ph1;
                *(uint4*)(dh + 8704 +  0) = pl0;
                *(uint4*)(dh + 8704 + 16) = pl1;
                __syncthreads();
            }
        }

        // ---- combine k-halves via smem ----
        if (kh == 1) {
            unsigned char* red = sm + R2_OFFRED + (((mq * 2 + nq) * 32 + lane) * 32);
            *(float4*)(red +  0) = make_float4(acc[0][0], acc[0][1], acc[0][2], acc[0][3]);
            *(float4*)(red + 16) = make_float4(acc[1][0], acc[1][1], acc[1][2], acc[1][3]);
        }
        __syncthreads();

        if (kh == 0) {
            const unsigned char* red = sm + R2_OFFRED + (((mq * 2 + nq) * 32 + lane) * 32);
            float4 r0 = *(const float4*)(red +  0);
            float4 r1 = *(const float4*)(red + 16);
            acc[0][0] += r0.x; acc[0][1] += r0.y; acc[0][2] += r0.z; acc[0][3] += r0.w;
            acc[1][0] += r1.x; acc[1][1] += r1.y; acc[1][2] += r1.z; acc[1][3] += r1.w;

            __nv_bfloat16* WH = g_hbf_hi[(t + 1) & 1];
            __nv_bfloat16* WL = g_hbf_lo[(t + 1) & 1];

            float a00 = tanhf(acc[0][0] + xp00.x), a01 = tanhf(acc[0][1] + xp00.y);
            float a80 = tanhf(acc[1][0] + xp01.x), a81 = tanhf(acc[1][1] + xp01.y);
            float b00 = tanhf(acc[0][2] + xp10.x), b01 = tanhf(acc[0][3] + xp10.y);
            float b80 = tanhf(acc[1][2] + xp11.x), b81 = tanhf(acc[1][3] + xp11.y);

            uint32_t ph, pl;
            size_t o00 = (size_t)erow * NDIM + ecol;
            size_t o01 = o00 + 8;
            size_t o10 = (size_t)(erow + 8) * NDIM + ecol;
            size_t o11 = o10 + 8;
            split2(a00, a01, ph, pl); *(uint32_t*)&WH[o00] = ph; *(uint32_t*)&WL[o00] = pl;
            split2(a80, a81, ph, pl); *(uint32_t*)&WH[o01] = ph; *(uint32_t*)&WL[o01] = pl;
            split2(b00, b01, ph, pl); *(uint32_t*)&WH[o10] = ph; *(uint32_t*)&WL[o10] = pl;
            split2(b80, b81, ph, pl); *(uint32_t*)&WH[o11] = ph; *(uint32_t*)&WL[o11] = pl;

            if (t == SEQ - 1) {
                *(float2*)(g_hfin + o00) = make_float2(a00, a01);
                *(float2*)(g_hfin + o01) = make_float2(a80, a81);
                *(float2*)(g_hfin + o10) = make_float2(b00, b01);
                *(float2*)(g_hfin + o11) = make_float2(b80, b81);
            }
        }
        __threadfence();
        grid_barrier();
    }
}

// ---------------------------------------------------------------------------
// Final: out = h_final @ W_hy + b_y
// ---------------------------------------------------------------------------
__global__ void __launch_bounds__(128) rnn_final(const float* __restrict__ W,
                                                 const float* __restrict__ bias,
                                                 float* __restrict__ out) {
    __shared__ float As[32 * 34];
    __shared__ float Bs[32 * 32];

    const float* __restrict__ H = g_hfin;

    const int tid = threadIdx.x;
    const int bx  = blockIdx.x;
    const int by  = blockIdx.y;

    const int rI = tid / 8;
    const int cI = (tid % 8) * 4;
    const int tr = tid / 8;
    const int tc = tid % 8;

    float acc[2][4];
#pragma unroll
    for (int i = 0; i < 2; i++)
#pragma unroll
        for (int q = 0; q < 4; q++) acc[i][q] = 0.0f;

    for (int bk = 0; bk < NDIM; bk += 32) {
#pragma unroll
        for (int rr = 0; rr < 2; rr++) {
            int rw = rI + rr * 16;
            float4 a = *(const float4*)(H + (by * 32 + rw) * NDIM + bk + cI);
            As[(cI + 0) * 34 + rw] = a.x;
            As[(cI + 1) * 34 + rw] = a.y;
            As[(cI + 2) * 34 + rw] = a.z;
            As[(cI + 3) * 34 + rw] = a.w;
            *(float4*)(Bs + rw * 32 + cI) =
                *(const float4*)(W + (size_t)(bk + rw) * NDIM + bx * 32 + cI);
        }
        __syncthreads();

#pragma unroll
        for (int k = 0; k < 32; k++) {
            float2 av = *(const float2*)(As + k * 34 + tr * 2);
            float4 bv = *(const float4*)(Bs + k * 32 + tc * 4);
            acc[0][0] += av.x * bv.x; acc[0][1] += av.x * bv.y;
            acc[0][2] += av.x * bv.z; acc[0][3] += av.x * bv.w;
            acc[1][0] += av.y * bv.x; acc[1][1] += av.y * bv.y;
            acc[1][2] += av.y * bv.z; acc[1][3] += av.y * bv.w;
        }
        __syncthreads();
    }

    const int col = bx * 32 + tc * 4;
    float4 bv4 = *(const float4*)(bias + col);
#pragma unroll
    for (int i = 0; i < 2; i++) {
        int row = by * 32 + tr * 2 + i;
        float4 v;
        v.x = acc[i][0] + bv4.x;
        v.y = acc[i][1] + bv4.y;
        v.z = acc[i][2] + bv4.z;
        v.w = acc[i][3] + bv4.w;
        *(float4*)(out + row * NDIM + col) = v;
    }
}

// ---------------------------------------------------------------------------
// kernel_launch — graph-capturable
// ---------------------------------------------------------------------------
extern "C" void kernel_launch(void* const* d_in, const int* in_sizes, int n_in,
                              void* d_out, int out_size) {
    (void)in_sizes; (void)n_in; (void)out_size;
    const float* x    = (const float*)d_in[0];
    const float* W_xh = (const float*)d_in[1];
    const float* W_hh = (const float*)d_in[2];
    const float* b_h  = (const float*)d_in[3];
    const float* W_hy = (const float*)d_in[4];
    const float* b_y  = (const float*)d_in[5];
    float* out = (float*)d_out;

    cudaFuncSetAttribute(xp_gemm_mma, cudaFuncAttributeMaxDynamicSharedMemorySize, XP_SMEM);
    cudaFuncSetAttribute(rnn_persistent2, cudaFuncAttributeMaxDynamicSharedMemorySize, R2_SMEM);

    zero_hbf<<<(BATCH * NDIM + 511) / 512, 512>>>();

    dim3 gridW(NDIM / 32, NDIM / 32);
    wprep<<<gridW, dim3(32, 8)>>>(W_xh, 0);
    wprep<<<gridW, dim3(32, 8)>>>(W_hh, 1);

    dim3 gridXP(NDIM / 128, (BATCH * SEQ) / 128);   // (8, 512)
    xp_gemm_mma<<<gridXP, 256, XP_SMEM>>>(x, b_h);

    rnn_persistent2<<<RGRID, 256, R2_SMEM>>>();

    dim3 gridFin(NDIM / 32, BATCH / 32);
    rnn_final<<<gridFin, 128>>>(W_hy, b_y, out);
}

// round 6
// speedup vs baseline: 2.8572x; 1.0100x over previous
#include <cuda_runtime.h>
#include <cuda_bf16.h>
#include <math.h>
#include <stdint.h>

#define BATCH 128
#define SEQ   512
#define NDIM  1024
#define RGRID 128          // persistent CTAs: 4 m-groups x 32 n-blocks

// ---------------------------------------------------------------------------
// Global scratch (allocation-free)
// ---------------------------------------------------------------------------
__device__ float g_xp[(size_t)BATCH * SEQ * NDIM];        // 256 MB
__device__ __nv_bfloat16 g_Wt_hi[(size_t)NDIM * NDIM];    // W_xh^T hi  [N][K]
__device__ __nv_bfloat16 g_Wt_lo[(size_t)NDIM * NDIM];
__device__ __nv_bfloat16 g_Whh_hi[(size_t)NDIM * NDIM];   // W_hh^T hi  [N][K]
__device__ __nv_bfloat16 g_Whh_lo[(size_t)NDIM * NDIM];
__device__ __nv_bfloat16 g_hbf_hi[2][BATCH * NDIM];       // ping-pong h hi
__device__ __nv_bfloat16 g_hbf_lo[2][BATCH * NDIM];       // ping-pong h lo
__device__ float g_hfin[BATCH * NDIM];                    // final h fp32
__device__ unsigned g_gcnt[4 * 32];                       // per-group counters (padded)
__device__ unsigned g_ggen[4 * 32];                       // per-group generations

// ---------------------------------------------------------------------------
// Helpers
// ---------------------------------------------------------------------------
__device__ __forceinline__ uint32_t smem_u32(const void* p) {
    uint32_t a;
    asm("{ .reg .u64 t; cvta.to.shared.u64 t, %1; cvt.u32.u64 %0, t; }"
        : "=r"(a) : "l"(p));
    return a;
}

__device__ __forceinline__ void ldsm4(uint32_t (&r)[4], uint32_t addr) {
    asm volatile("ldmatrix.sync.aligned.m8n8.x4.shared.b16 {%0,%1,%2,%3}, [%4];"
                 : "=r"(r[0]), "=r"(r[1]), "=r"(r[2]), "=r"(r[3]) : "r"(addr));
}

__device__ __forceinline__ void mma_bf16(float (&d)[4], const uint32_t (&a)[4],
                                         const uint32_t b0, const uint32_t b1) {
    asm volatile(
        "mma.sync.aligned.m16n8k16.row.col.f32.bf16.bf16.f32 "
        "{%0,%1,%2,%3}, {%4,%5,%6,%7}, {%8,%9}, {%0,%1,%2,%3};"
        : "+f"(d[0]), "+f"(d[1]), "+f"(d[2]), "+f"(d[3])
        : "r"(a[0]), "r"(a[1]), "r"(a[2]), "r"(a[3]), "r"(b0), "r"(b1));
}

#define CP_ASYNC16(dst, src) \
    asm volatile("cp.async.cg.shared.global [%0], [%1], 16;" \
                 :: "r"(dst), "l"(src) : "memory")
#define CP_COMMIT() asm volatile("cp.async.commit_group;" ::: "memory")
#define CP_WAIT0()  asm volatile("cp.async.wait_group 0;" ::: "memory")

// split 8 fp32 -> 8 bf16 hi + 8 bf16 lo (packed uint4 each)
__device__ __forceinline__ void split8(float4 f0, float4 f1, uint4& hi, uint4& lo) {
    float f[8] = {f0.x, f0.y, f0.z, f0.w, f1.x, f1.y, f1.z, f1.w};
    unsigned short h[8], l[8];
#pragma unroll
    for (int i = 0; i < 8; i++) {
        __nv_bfloat16 bh = __float2bfloat16_rn(f[i]);
        float r = f[i] - __bfloat162float(bh);
        h[i] = __bfloat16_as_ushort(bh);
        l[i] = __bfloat16_as_ushort(__float2bfloat16_rn(r));
    }
    hi.x = (uint32_t)h[0] | ((uint32_t)h[1] << 16);
    hi.y = (uint32_t)h[2] | ((uint32_t)h[3] << 16);
    hi.z = (uint32_t)h[4] | ((uint32_t)h[5] << 16);
    hi.w = (uint32_t)h[6] | ((uint32_t)h[7] << 16);
    lo.x = (uint32_t)l[0] | ((uint32_t)l[1] << 16);
    lo.y = (uint32_t)l[2] | ((uint32_t)l[3] << 16);
    lo.z = (uint32_t)l[4] | ((uint32_t)l[5] << 16);
    lo.w = (uint32_t)l[6] | ((uint32_t)l[7] << 16);
}

// split 2 fp32 -> packed bf16x2 hi + lo
__device__ __forceinline__ void split2(float a, float b, uint32_t& hi, uint32_t& lo) {
    __nv_bfloat16 ah = __float2bfloat16_rn(a), bh = __float2bfloat16_rn(b);
    float ar = a - __bfloat162float(ah), br = b - __bfloat162float(bh);
    hi = (uint32_t)__bfloat16_as_ushort(ah) |
         ((uint32_t)__bfloat16_as_ushort(bh) << 16);
    lo = (uint32_t)__bfloat16_as_ushort(__float2bfloat16_rn(ar)) |
         ((uint32_t)__bfloat16_as_ushort(__float2bfloat16_rn(br)) << 16);
}

// 32-CTA group barrier (release/acquire via thread-0 fence; CG grid.sync pattern)
__device__ __forceinline__ void group_barrier(int grp) {
    __syncthreads();
    if (threadIdx.x == 0) {
        unsigned* cnt = &g_gcnt[grp * 32];
        volatile unsigned* gen = (volatile unsigned*)&g_ggen[grp * 32];
        unsigned myg = *gen;
        __threadfence();                       // release (cumulative)
        if (atomicAdd(cnt, 1) == 31) {
            atomicExch(cnt, 0);
            __threadfence();
            atomicAdd((unsigned*)gen, 1);      // release generation
        } else {
            while (*gen == myg) { }
            __threadfence();                   // acquire
        }
    }
    __syncthreads();
}

// ---------------------------------------------------------------------------
// Setup kernels
// ---------------------------------------------------------------------------
__global__ void zero_hbf() {
    int idx = blockIdx.x * blockDim.x + threadIdx.x;
    if (idx < BATCH * NDIM) {
        g_hbf_hi[0][idx] = __float2bfloat16_rn(0.0f);
        g_hbf_lo[0][idx] = __float2bfloat16_rn(0.0f);
    }
}

// Transpose + split W [K,N] -> dst_hi/lo [N,K] bf16.  which: 0 = W_xh, 1 = W_hh
__global__ void wprep(const float* __restrict__ W, int which) {
    __shared__ float t[32][33];
    __nv_bfloat16* dhi = which ? g_Whh_hi : g_Wt_hi;
    __nv_bfloat16* dlo = which ? g_Whh_lo : g_Wt_lo;
    int tx = threadIdx.x, ty = threadIdx.y;
    int nb = blockIdx.x * 32, kb = blockIdx.y * 32;
#pragma unroll
    for (int i = ty; i < 32; i += 8)
        t[i][tx] = W[(size_t)(kb + i) * NDIM + nb + tx];
    __syncthreads();
#pragma unroll
    for (int i = ty; i < 32; i += 8) {
        float f = t[tx][i];
        __nv_bfloat16 bh = __float2bfloat16_rn(f);
        float r = f - __bfloat162float(bh);
        size_t off = (size_t)(nb + i) * NDIM + kb + tx;
        dhi[off] = bh;
        dlo[off] = __float2bfloat16_rn(r);
    }
}

// ---------------------------------------------------------------------------
// XP GEMM via mma.sync bf16-split (unchanged — near floor for mma.sync)
// ---------------------------------------------------------------------------
#define XP_ARR  10240
#define XP_BUF  (4 * XP_ARR)
#define XP_SMEM (2 * XP_BUF)

__global__ void __launch_bounds__(256) xp_gemm_mma(const float* __restrict__ A,
                                                   const float* __restrict__ bias) {
    extern __shared__ __align__(16) unsigned char sm[];
    const uint32_t sb = smem_u32(sm);
    const int tid = threadIdx.x, wid = tid >> 5, lane = tid & 31;
    const int cCol = blockIdx.x, cRow = blockIdx.y;
    const int wm = (wid >> 2) * 64;
    const int wn = (wid & 3) * 32;

    const int lrow = tid >> 1;
    const int lhf  = tid & 1;
    const float* Ag = A + (size_t)(cRow * 128 + lrow) * NDIM + lhf * 16;
    const __nv_bfloat16* Bhg = g_Wt_hi + (size_t)(cCol * 128 + lrow) * NDIM + lhf * 16;
    const __nv_bfloat16* Blg = g_Wt_lo + (size_t)(cCol * 128 + lrow) * NDIM + lhf * 16;
    unsigned char* st_a = sm + lrow * 80 + lhf * 32;
    unsigned char* st_b = sm + 2 * XP_ARR + lrow * 80 + lhf * 32;

    float acc[4][4][4];
#pragma unroll
    for (int i = 0; i < 4; i++)
#pragma unroll
        for (int j = 0; j < 4; j++)
#pragma unroll
            for (int q = 0; q < 4; q++) acc[i][j][q] = 0.0f;

    {
        float4 f0 = *(const float4*)(Ag + 0);
        float4 f1 = *(const float4*)(Ag + 4);
        float4 f2 = *(const float4*)(Ag + 8);
        float4 f3 = *(const float4*)(Ag + 12);
        uint4 h0, l0, h1, l1;
        split8(f0, f1, h0, l0);
        split8(f2, f3, h1, l1);
        *(uint4*)(st_a +  0) = h0; *(uint4*)(st_a + 16) = h1;
        *(uint4*)(st_a + XP_ARR +  0) = l0; *(uint4*)(st_a + XP_ARR + 16) = l1;
        uint4 bh0 = *(const uint4*)(Bhg);     uint4 bh1 = *(const uint4*)(Bhg + 8);
        uint4 bl0 = *(const uint4*)(Blg);     uint4 bl1 = *(const uint4*)(Blg + 8);
        *(uint4*)(st_b +  0) = bh0; *(uint4*)(st_b + 16) = bh1;
        *(uint4*)(st_b + XP_ARR +  0) = bl0; *(uint4*)(st_b + XP_ARR + 16) = bl1;
    }
    __syncthreads();

#pragma unroll 1
    for (int ko = 0; ko < 32; ko++) {
        const int buf = ko & 1;
        float4 f0, f1, f2, f3;
        uint4 pbh0, pbh1, pbl0, pbl1;
        if (ko < 31) {
            const float* Ap = Ag + (ko + 1) * 32;
            f0 = *(const float4*)(Ap + 0);  f1 = *(const float4*)(Ap + 4);
            f2 = *(const float4*)(Ap + 8);  f3 = *(const float4*)(Ap + 12);
            pbh0 = *(const uint4*)(Bhg + (ko + 1) * 32);
            pbh1 = *(const uint4*)(Bhg + (ko + 1) * 32 + 8);
            pbl0 = *(const uint4*)(Blg + (ko + 1) * 32);
            pbl1 = *(const uint4*)(Blg + (ko + 1) * 32 + 8);
        }

        const uint32_t base = sb + buf * XP_BUF;
#pragma unroll
        for (int s = 0; s < 2; s++) {
            const uint32_t k0b = s * 32;
            uint32_t ah[4][4], al[4][4];
#pragma unroll
            for (int mi = 0; mi < 4; mi++) {
                uint32_t ad = base + (wm + mi * 16 + (lane & 15)) * 80 + k0b + (lane >> 4) * 16;
                ldsm4(ah[mi], ad);
                ldsm4(al[mi], ad + XP_ARR);
            }
            uint32_t bh[4][2], bl[4][2];
#pragma unroll
            for (int nb = 0; nb < 2; nb++) {
                uint32_t bd = base + 2 * XP_ARR +
                              (wn + nb * 16 + (lane & 7) + ((lane >> 4) << 3)) * 80 +
                              k0b + (((lane >> 3) & 1) << 4);
                uint32_t r[4];
                ldsm4(r, bd);
                bh[nb * 2 + 0][0] = r[0]; bh[nb * 2 + 0][1] = r[1];
                bh[nb * 2 + 1][0] = r[2]; bh[nb * 2 + 1][1] = r[3];
                ldsm4(r, bd + XP_ARR);
                bl[nb * 2 + 0][0] = r[0]; bl[nb * 2 + 0][1] = r[1];
                bl[nb * 2 + 1][0] = r[2]; bl[nb * 2 + 1][1] = r[3];
            }
#pragma unroll
            for (int mi = 0; mi < 4; mi++)
#pragma unroll
                for (int nj = 0; nj < 4; nj++) {
                    mma_bf16(acc[mi][nj], ah[mi], bh[nj][0], bh[nj][1]);
                    mma_bf16(acc[mi][nj], ah[mi], bl[nj][0], bl[nj][1]);
                    mma_bf16(acc[mi][nj], al[mi], bh[nj][0], bh[nj][1]);
                }
        }

        if (ko < 31) {
            unsigned char* da = st_a + (buf ^ 1) * XP_BUF;
            unsigned char* db = st_b + (buf ^ 1) * XP_BUF;
            uint4 h0, l0, h1, l1;
            split8(f0, f1, h0, l0);
            split8(f2, f3, h1, l1);
            *(uint4*)(da +  0) = h0; *(uint4*)(da + 16) = h1;
            *(uint4*)(da + XP_ARR +  0) = l0; *(uint4*)(da + XP_ARR + 16) = l1;
            *(uint4*)(db +  0) = pbh0; *(uint4*)(db + 16) = pbh1;
            *(uint4*)(db + XP_ARR +  0) = pbl0; *(uint4*)(db + XP_ARR + 16) = pbl1;
            __syncthreads();
        }
    }

#pragma unroll
    for (int mi = 0; mi < 4; mi++) {
        int row = cRow * 128 + wm + mi * 16 + (lane >> 2);
#pragma unroll
        for (int nj = 0; nj < 4; nj++) {
            int col = cCol * 128 + wn + nj * 8 + (lane & 3) * 2;
            float b0 = bias[col], b1 = bias[col + 1];
            float2 v0 = {acc[mi][nj][0] + b0, acc[mi][nj][1] + b1};
            float2 v1 = {acc[mi][nj][2] + b0, acc[mi][nj][3] + b1};
            *(float2*)(g_xp + (size_t)row * NDIM + col) = v0;
            *(float2*)(g_xp + (size_t)(row + 8) * NDIM + col) = v1;
        }
    }
}

// ---------------------------------------------------------------------------
// Persistent recurrence v3: 128 CTAs = 4 groups x 32; 32x32 tile, full K.
// Per-group (32-CTA) barrier, cp.async 256-k chunks, thread0-only fences.
// smem: W hi/lo 2x66048 | h 2 bufs x (hi 16896 + lo 16896) | reduce 4096
// ---------------------------------------------------------------------------
#define R3_WS     2064                 // W row stride (1024*2 + 16 pad)
#define R3_HS     528                  // h row stride (256*2 + 16 pad)
#define R3_OFFW   0
#define R3_OFFWL  66048
#define R3_OFFH   132096
#define R3_HBUF   33792                // hi 16896 + lo 16896
#define R3_HLO    16896
#define R3_OFFRED 199680
#define R3_SMEM   203776

__global__ void __launch_bounds__(256) rnn_persistent3() {
    extern __shared__ __align__(16) unsigned char sm[];
    const uint32_t sb = smem_u32(sm);
    const int tid = threadIdx.x, wid = tid >> 5, lane = tid & 31;
    const int r  = blockIdx.x;
    const int mi = r >> 5;          // m-group 0..3
    const int nj = r & 31;          // n-block 0..31
    const int mq = (wid >> 1) & 1;  // quadrant m
    const int nq = wid & 1;         // quadrant n
    const int kh = wid >> 2;        // k-half 0/1

    // ---- load W_hh^T rows [nj*32, +32) into smem (once, persistent) ----
    {
        const int n  = tid >> 3;             // 0..31
        const int sg = (tid & 7) * 256;      // byte offset within 2048B row
        const unsigned char* gh = (const unsigned char*)(g_Whh_hi + (size_t)(nj * 32 + n) * NDIM) + sg;
        const unsigned char* gl = (const unsigned char*)(g_Whh_lo + (size_t)(nj * 32 + n) * NDIM) + sg;
        uint32_t dh = sb + R3_OFFW  + n * R3_WS + sg;
        uint32_t dl = sb + R3_OFFWL + n * R3_WS + sg;
#pragma unroll
        for (int i = 0; i < 16; i++) {
            CP_ASYNC16(dh + i * 16, gh + i * 16);
            CP_ASYNC16(dl + i * 16, gl + i * 16);
        }
        CP_COMMIT();
    }

    // h loader geometry: row = tid>>3 (0..31), 64B segment = (tid&7)*64 of 512B row
    const int hrow = tid >> 3;
    const int hsg  = (tid & 7) * 64;

    // epilogue geometry (kh==0 warps)
    const int erow = mi * 32 + mq * 16 + (lane >> 2);
    const int ecol = nj * 32 + nq * 16 + (lane & 3) * 2;

    CP_WAIT0();
    __syncthreads();

#pragma unroll 1
    for (int t = 0; t < SEQ; t++) {
        const unsigned char* HgH =
            (const unsigned char*)(g_hbf_hi[t & 1] + (size_t)(mi * 32 + hrow) * NDIM) + hsg;
        const unsigned char* HgL =
            (const unsigned char*)(g_hbf_lo[t & 1] + (size_t)(mi * 32 + hrow) * NDIM) + hsg;
        const uint32_t hd = sb + R3_OFFH + hrow * R3_HS + hsg;

        // prologue: chunk 0 -> buf 0
#pragma unroll
        for (int i = 0; i < 4; i++) {
            CP_ASYNC16(hd + i * 16,          HgH + i * 16);
            CP_ASYNC16(hd + R3_HLO + i * 16, HgL + i * 16);
        }
        CP_COMMIT();

        // xp prefetch (combiner warps)
        float2 xp00, xp01, xp10, xp11;
        if (kh == 0) {
            const float* b0 = g_xp + ((size_t)erow * SEQ + t) * NDIM;
            const float* b1 = g_xp + ((size_t)(erow + 8) * SEQ + t) * NDIM;
            xp00 = *(const float2*)(b0 + ecol);
            xp01 = *(const float2*)(b0 + ecol + 8);
            xp10 = *(const float2*)(b1 + ecol);
            xp11 = *(const float2*)(b1 + ecol + 8);
        }

        CP_WAIT0();
        __syncthreads();

        float acc[2][4];
#pragma unroll
        for (int f = 0; f < 2; f++)
#pragma unroll
            for (int q = 0; q < 4; q++) acc[f][q] = 0.0f;

#pragma unroll 1
        for (int ks = 0; ks < 4; ks++) {
            const int buf = ks & 1;

            if (ks < 3) {   // cp.async next chunk -> other buffer
                const uint32_t hd2 = sb + R3_OFFH + (buf ^ 1) * R3_HBUF + hrow * R3_HS + hsg;
#pragma unroll
                for (int i = 0; i < 4; i++) {
                    CP_ASYNC16(hd2 + i * 16,          HgH + (ks + 1) * 512 + i * 16);
                    CP_ASYNC16(hd2 + R3_HLO + i * 16, HgL + (ks + 1) * 512 + i * 16);
                }
                CP_COMMIT();
            }

            const uint32_t hbase = sb + R3_OFFH + buf * R3_HBUF;
#pragma unroll
            for (int kk = 0; kk < 8; kk++) {
                const uint32_t kby = kh * 256 + kk * 32;           // byte offset in 512B chunk row
                const uint32_t gkb = ks * 512 + kby;               // byte offset in 2048B W row
                uint32_t ah[4], al[4];
                uint32_t ad = hbase + (mq * 16 + (lane & 15)) * R3_HS + kby + (lane >> 4) * 16;
                ldsm4(ah, ad);
                ldsm4(al, ad + R3_HLO);

                uint32_t bh[4], bl[4];
                uint32_t bd = sb + R3_OFFW +
                              (nq * 16 + (lane & 7) + ((lane >> 4) << 3)) * R3_WS +
                              gkb + (((lane >> 3) & 1) << 4);
                ldsm4(bh, bd);
                ldsm4(bl, bd + (R3_OFFWL - R3_OFFW));

#pragma unroll
                for (int f = 0; f < 2; f++) {
                    mma_bf16(acc[f], ah, bh[f * 2], bh[f * 2 + 1]);
                    mma_bf16(acc[f], ah, bl[f * 2], bl[f * 2 + 1]);
                    mma_bf16(acc[f], al, bh[f * 2], bh[f * 2 + 1]);
                }
            }

            if (ks < 3) {
                CP_WAIT0();
                __syncthreads();
            }
        }

        // ---- combine k-halves via smem ----
        if (kh == 1) {
            unsigned char* red = sm + R3_OFFRED + (((mq * 2 + nq) * 32 + lane) * 32);
            *(float4*)(red +  0) = make_float4(acc[0][0], acc[0][1], acc[0][2], acc[0][3]);
            *(float4*)(red + 16) = make_float4(acc[1][0], acc[1][1], acc[1][2], acc[1][3]);
        }
        __syncthreads();

        if (kh == 0) {
            const unsigned char* red = sm + R3_OFFRED + (((mq * 2 + nq) * 32 + lane) * 32);
            float4 r0 = *(const float4*)(red +  0);
            float4 r1 = *(const float4*)(red + 16);
            acc[0][0] += r0.x; acc[0][1] += r0.y; acc[0][2] += r0.z; acc[0][3] += r0.w;
            acc[1][0] += r1.x; acc[1][1] += r1.y; acc[1][2] += r1.z; acc[1][3] += r1.w;

            __nv_bfloat16* WH = g_hbf_hi[(t + 1) & 1];
            __nv_bfloat16* WL = g_hbf_lo[(t + 1) & 1];

            float a00 = tanhf(acc[0][0] + xp00.x), a01 = tanhf(acc[0][1] + xp00.y);
            float a80 = tanhf(acc[1][0] + xp01.x), a81 = tanhf(acc[1][1] + xp01.y);
            float b00 = tanhf(acc[0][2] + xp10.x), b01 = tanhf(acc[0][3] + xp10.y);
            float b80 = tanhf(acc[1][2] + xp11.x), b81 = tanhf(acc[1][3] + xp11.y);

            uint32_t ph, pl;
            size_t o00 = (size_t)erow * NDIM + ecol;
            size_t o01 = o00 + 8;
            size_t o10 = (size_t)(erow + 8) * NDIM + ecol;
            size_t o11 = o10 + 8;
            split2(a00, a01, ph, pl); *(uint32_t*)&WH[o00] = ph; *(uint32_t*)&WL[o00] = pl;
            split2(a80, a81, ph, pl); *(uint32_t*)&WH[o01] = ph; *(uint32_t*)&WL[o01] = pl;
            split2(b00, b01, ph, pl); *(uint32_t*)&WH[o10] = ph; *(uint32_t*)&WL[o10] = pl;
            split2(b80, b81, ph, pl); *(uint32_t*)&WH[o11] = ph; *(uint32_t*)&WL[o11] = pl;

            if (t == SEQ - 1) {
                *(float2*)(g_hfin + o00) = make_float2(a00, a01);
                *(float2*)(g_hfin + o01) = make_float2(a80, a81);
                *(float2*)(g_hfin + o10) = make_float2(b00, b01);
                *(float2*)(g_hfin + o11) = make_float2(b80, b81);
            }
        }

        group_barrier(mi);
    }
}

// ---------------------------------------------------------------------------
// Final: out = h_final @ W_hy + b_y
// ---------------------------------------------------------------------------
__global__ void __launch_bounds__(128) rnn_final(const float* __restrict__ W,
                                                 const float* __restrict__ bias,
                                                 float* __restrict__ out) {
    __shared__ float As[32 * 34];
    __shared__ float Bs[32 * 32];

    const float* __restrict__ H = g_hfin;

    const int tid = threadIdx.x;
    const int bx  = blockIdx.x;
    const int by  = blockIdx.y;

    const int rI = tid / 8;
    const int cI = (tid % 8) * 4;
    const int tr = tid / 8;
    const int tc = tid % 8;

    float acc[2][4];
#pragma unroll
    for (int i = 0; i < 2; i++)
#pragma unroll
        for (int q = 0; q < 4; q++) acc[i][q] = 0.0f;

    for (int bk = 0; bk < NDIM; bk += 32) {
#pragma unroll
        for (int rr = 0; rr < 2; rr++) {
            int rw = rI + rr * 16;
            float4 a = *(const float4*)(H + (by * 32 + rw) * NDIM + bk + cI);
            As[(cI + 0) * 34 + rw] = a.x;
            As[(cI + 1) * 34 + rw] = a.y;
            As[(cI + 2) * 34 + rw] = a.z;
            As[(cI + 3) * 34 + rw] = a.w;
            *(float4*)(Bs + rw * 32 + cI) =
                *(const float4*)(W + (size_t)(bk + rw) * NDIM + bx * 32 + cI);
        }
        __syncthreads();

#pragma unroll
        for (int k = 0; k < 32; k++) {
            float2 av = *(const float2*)(As + k * 34 + tr * 2);
            float4 bv = *(const float4*)(Bs + k * 32 + tc * 4);
            acc[0][0] += av.x * bv.x; acc[0][1] += av.x * bv.y;
            acc[0][2] += av.x * bv.z; acc[0][3] += av.x * bv.w;
            acc[1][0] += av.y * bv.x; acc[1][1] += av.y * bv.y;
            acc[1][2] += av.y * bv.z; acc[1][3] += av.y * bv.w;
        }
        __syncthreads();
    }

    const int col = bx * 32 + tc * 4;
    float4 bv4 = *(const float4*)(bias + col);
#pragma unroll
    for (int i = 0; i < 2; i++) {
        int row = by * 32 + tr * 2 + i;
        float4 v;
        v.x = acc[i][0] + bv4.x;
        v.y = acc[i][1] + bv4.y;
        v.z = acc[i][2] + bv4.z;
        v.w = acc[i][3] + bv4.w;
        *(float4*)(out + row * NDIM + col) = v;
    }
}

// ---------------------------------------------------------------------------
// kernel_launch — graph-capturable
// ---------------------------------------------------------------------------
extern "C" void kernel_launch(void* const* d_in, const int* in_sizes, int n_in,
                              void* d_out, int out_size) {
    (void)in_sizes; (void)n_in; (void)out_size;
    const float* x    = (const float*)d_in[0];
    const float* W_xh = (const float*)d_in[1];
    const float* W_hh = (const float*)d_in[2];
    const float* b_h  = (const float*)d_in[3];
    const float* W_hy = (const float*)d_in[4];
    const float* b_y  = (const float*)d_in[5];
    float* out = (float*)d_out;

    cudaFuncSetAttribute(xp_gemm_mma, cudaFuncAttributeMaxDynamicSharedMemorySize, XP_SMEM);
    cudaFuncSetAttribute(rnn_persistent3, cudaFuncAttributeMaxDynamicSharedMemorySize, R3_SMEM);

    zero_hbf<<<(BATCH * NDIM + 511) / 512, 512>>>();

    dim3 gridW(NDIM / 32, NDIM / 32);
    wprep<<<gridW, dim3(32, 8)>>>(W_xh, 0);
    wprep<<<gridW, dim3(32, 8)>>>(W_hh, 1);

    dim3 gridXP(NDIM / 128, (BATCH * SEQ) / 128);   // (8, 512)
    xp_gemm_mma<<<gridXP, 256, XP_SMEM>>>(x, b_h);

    rnn_persistent3<<<RGRID, 256, R3_SMEM>>>();

    dim3 gridFin(NDIM / 32, BATCH / 32);
    rnn_final<<<gridFin, 128>>>(W_hy, b_y, out);
}